// round 2
// baseline (speedup 1.0000x reference)
#include <cuda_runtime.h>
#include <math.h>

#define NROWS 16384
#define Tt 15
#define EPSg 1e-10f

// ---------------- scratch (static device arrays; no allocation) ----------------
__device__ float g_q[NROWS*64];
__device__ float g_k[NROWS*64];
__device__ float g_v[NROWS*64];
__device__ float g_Gf [NROWS*192];
__device__ float g_Cbf[NROWS*192];
__device__ float g_Gb [NROWS*192];
__device__ float g_Cbb[NROWS*192];
__device__ float g_lf[NROWS*2*Tt];
__device__ float g_hw[NROWS*Tt];

__device__ __forceinline__ float sigm(float x){ return 1.0f/(1.0f+__expf(-x)); }
__device__ __forceinline__ float tanh_(float x){ return 2.0f/(1.0f+__expf(-2.0f*x)) - 1.0f; }

// =====================================================================
// K1: h_enc = relu(obs@W_enc+b_enc); then q,k,v and GRU input projections
//     Cb* = h@WihL^T + bih   (step-invariant part)
//     G*  = h@WihR^T         (neighbor part)
// block = 64 rows, 256 threads; smem: Os,Hs,Wt (3 * 64*65 floats)
// =====================================================================
__global__ __launch_bounds__(256,1)
void k_proj(const float* __restrict__ obs,
            const float* __restrict__ W_enc, const float* __restrict__ b_enc,
            const float* __restrict__ Wq, const float* __restrict__ Wk,
            const float* __restrict__ Wv, const float* __restrict__ b_v,
            const float* __restrict__ Wih_f, const float* __restrict__ bih_f,
            const float* __restrict__ Wih_b, const float* __restrict__ bih_b)
{
    extern __shared__ float sm[];
    float* Os = sm;                 // 64*65
    float* Hs = sm + 64*65;         // 64*65
    float* Wt = sm + 2*64*65;       // 64*65
    const int tid = threadIdx.x;
    const int rbase = blockIdx.x * 64;
    const int ty = tid >> 4, tx = tid & 15;
    const int r0 = ty * 4;

    for (int idx = tid; idx < 4096; idx += 256) {
        int r = idx >> 6, c = idx & 63;
        Os[r*65+c] = obs[(rbase+r)*64 + c];
        Wt[r*65+c] = W_enc[idx];             // W_enc[d*64+c] -> Wt[d][c]
    }
    __syncthreads();

    {   // h_enc tile
        float acc[4][4];
        #pragma unroll
        for (int i=0;i<4;i++){ acc[i][0]=0.f;acc[i][1]=0.f;acc[i][2]=0.f;acc[i][3]=0.f; }
        for (int dd=0; dd<64; ++dd){
            float a0=Os[(r0+0)*65+dd], a1=Os[(r0+1)*65+dd], a2=Os[(r0+2)*65+dd], a3=Os[(r0+3)*65+dd];
            #pragma unroll
            for (int j=0;j<4;j++){
                float b = Wt[dd*65 + tx + 16*j];
                acc[0][j] += a0*b; acc[1][j] += a1*b; acc[2][j] += a2*b; acc[3][j] += a3*b;
            }
        }
        #pragma unroll
        for (int j=0;j<4;j++){
            int c = tx + 16*j;
            float be = b_enc[c];
            #pragma unroll
            for (int i=0;i<4;i++) Hs[(r0+i)*65+c] = fmaxf(acc[i][j] + be, 0.0f);
        }
    }
    __syncthreads();

    // 15 projection segments of 64 output columns each
    for (int s = 0; s < 15; ++s){
        const float* Wsrc; const float* bias=nullptr; int mode; int stride; int colBase=0; float* dst; int doRelu=0;
        if      (s==0){ Wsrc=Wq;    dst=g_q;   stride=64;  mode=0; }
        else if (s==1){ Wsrc=Wk;    dst=g_k;   stride=64;  mode=0; }
        else if (s==2){ Wsrc=Wv;    dst=g_v;   stride=64;  mode=0; bias=b_v; doRelu=1; }
        else if (s<6 ){ Wsrc=Wih_f; dst=g_Cbf; stride=192; colBase=(s-3 )*64; mode=1; bias=bih_f; }
        else if (s<9 ){ Wsrc=Wih_f; dst=g_Gf;  stride=192; colBase=(s-6 )*64; mode=2; }
        else if (s<12){ Wsrc=Wih_b; dst=g_Cbb; stride=192; colBase=(s-9 )*64; mode=1; bias=bih_b; }
        else          { Wsrc=Wih_b; dst=g_Gb;  stride=192; colBase=(s-12)*64; mode=2; }

        for (int idx = tid; idx < 4096; idx += 256){
            int hi = idx >> 6, lo = idx & 63;
            if (mode==0) Wt[hi*65+lo] = Wsrc[idx];                       // Wt[d][c]=W[d*64+c]
            else {
                // hi = gate col (g'), lo = d ; Wih[(colBase+g')*128 + d (+64 for right half)]
                int off = (colBase+hi)*128 + lo + (mode==2 ? 64 : 0);
                Wt[lo*65+hi] = Wsrc[off];                                // Wt[d][g']
            }
        }
        __syncthreads();

        float acc[4][4];
        #pragma unroll
        for (int i=0;i<4;i++){ acc[i][0]=0.f;acc[i][1]=0.f;acc[i][2]=0.f;acc[i][3]=0.f; }
        for (int dd=0; dd<64; ++dd){
            float a0=Hs[(r0+0)*65+dd], a1=Hs[(r0+1)*65+dd], a2=Hs[(r0+2)*65+dd], a3=Hs[(r0+3)*65+dd];
            #pragma unroll
            for (int j=0;j<4;j++){
                float b = Wt[dd*65 + tx + 16*j];
                acc[0][j] += a0*b; acc[1][j] += a1*b; acc[2][j] += a2*b; acc[3][j] += a3*b;
            }
        }
        #pragma unroll
        for (int j=0;j<4;j++){
            int c = tx + 16*j;
            float bb = bias ? bias[colBase + c] : 0.0f;
            #pragma unroll
            for (int i=0;i<4;i++){
                float v = acc[i][j] + bb;
                if (doRelu) v = fmaxf(v, 0.0f);
                dst[(rbase+r0+i)*stride + colBase + c] = v;
            }
        }
        __syncthreads();
    }
}

// =====================================================================
// K2/K3: one GRU direction. Block = 64 rows (4 batches), 256 threads.
// smem: Gs,Cbs,Ws (64*196 each) + hs (64*65)  ~= 163 KB
// gi_t[row] = Cbs[row] + Gs[neighbor(row,t)] ; gh via in-smem GEMM.
// Per-step projection onto W_hard half -> lf (fwd) / logits+gumbel->hard_w (bwd)
// =====================================================================
template<int FWD>
__global__ __launch_bounds__(256,1)
void k_gru(const float* __restrict__ Whh, const float* __restrict__ bhh,
           const float* __restrict__ W_hard, const float* __restrict__ b_hard,
           const float* __restrict__ gum)
{
    extern __shared__ float sm[];
    float* Gs  = sm;                  // 64*196
    float* Cbs = sm + 64*196;         // 64*196
    float* Ws  = sm + 2*64*196;       // 64*196 : Ws[d][g] = Whh[g][d]
    float* hs  = sm + 3*64*196;       // 64*65
    const int tid = threadIdx.x;
    const int rbase = blockIdx.x * 64;
    const int ty = tid >> 4, tx = tid & 15;
    const int r0 = ty*4;
    const float* Gsrc  = FWD ? g_Gf  : g_Gb;
    const float* Cbsrc = FWD ? g_Cbf : g_Cbb;

    for (int idx = tid; idx < 64*192; idx += 256){
        int r = idx / 192, g = idx - r*192;
        Gs [r*196+g] = Gsrc [(rbase+r)*192+g];
        Cbs[r*196+g] = Cbsrc[(rbase+r)*192+g];
    }
    for (int idx = tid; idx < 192*64; idx += 256){
        int g = idx >> 6, d = idx & 63;
        Ws[d*196+g] = Whh[idx];
    }
    for (int idx = tid; idx < 64*65; idx += 256) hs[idx] = 0.0f;

    float br_[4], bz_[4], bn_[4], w0_[4], w1_[4];
    #pragma unroll
    for (int k=0;k<4;k++){
        int d = tx + 16*k;
        br_[k]=bhh[d]; bz_[k]=bhh[d+64]; bn_[k]=bhh[d+128];
        int wr = FWD ? d : (64+d);
        w0_[k]=W_hard[wr*2]; w1_[k]=W_hard[wr*2+1];
    }
    const float bh0 = b_hard[0], bh1 = b_hard[1];
    __syncthreads();

    for (int step=0; step<Tt; ++step){
        const int t = FWD ? step : (Tt-1-step);
        float ar[4][4], az[4][4], an[4][4];
        #pragma unroll
        for (int i=0;i<4;i++)
            #pragma unroll
            for (int k=0;k<4;k++){ ar[i][k]=0.f; az[i][k]=0.f; an[i][k]=0.f; }

        for (int dd=0; dd<64; ++dd){
            float a0=hs[(r0+0)*65+dd], a1=hs[(r0+1)*65+dd], a2=hs[(r0+2)*65+dd], a3=hs[(r0+3)*65+dd];
            #pragma unroll
            for (int k=0;k<4;k++){
                int c = tx+16*k;
                float wr = Ws[dd*196+c], wz = Ws[dd*196+c+64], wn = Ws[dd*196+c+128];
                ar[0][k]+=a0*wr; ar[1][k]+=a1*wr; ar[2][k]+=a2*wr; ar[3][k]+=a3*wr;
                az[0][k]+=a0*wz; az[1][k]+=a1*wz; az[2][k]+=a2*wz; az[3][k]+=a3*wz;
                an[0][k]+=a0*wn; an[1][k]+=a1*wn; an[2][k]+=a2*wn; an[3][k]+=a3*wn;
            }
        }

        float hnew[4][4], l0[4], l1[4];
        #pragma unroll
        for (int i=0;i<4;i++){ l0[i]=0.f; l1[i]=0.f; }
        #pragma unroll
        for (int i=0;i<4;i++){
            int rl = r0+i;
            int ii = rl & 15;
            int jl = (rl & 48) + t + (t>=ii ? 1 : 0);   // neighbor row in block
            #pragma unroll
            for (int k=0;k<4;k++){
                int d = tx+16*k;
                float ir  = Cbs[rl*196+d]     + Gs[jl*196+d];
                float iz  = Cbs[rl*196+d+64]  + Gs[jl*196+d+64];
                float inn = Cbs[rl*196+d+128] + Gs[jl*196+d+128];
                float r = sigm(ir + ar[i][k] + br_[k]);
                float z = sigm(iz + az[i][k] + bz_[k]);
                float n = tanh_(inn + r*(an[i][k] + bn_[k]));
                float ho = hs[rl*65+d];
                float hv = (1.0f - z)*n + z*ho;
                hnew[i][k] = hv;
                l0[i] += hv * w0_[k];
                l1[i] += hv * w1_[k];
            }
        }
        __syncthreads();
        #pragma unroll
        for (int i=0;i<4;i++)
            #pragma unroll
            for (int k=0;k<4;k++)
                hs[(r0+i)*65 + tx + 16*k] = hnew[i][k];

        #pragma unroll
        for (int off=8; off>=1; off>>=1){
            #pragma unroll
            for (int i=0;i<4;i++){
                l0[i] += __shfl_xor_sync(0xffffffffu, l0[i], off);
                l1[i] += __shfl_xor_sync(0xffffffffu, l1[i], off);
            }
        }
        if (tx == 0){
            #pragma unroll
            for (int i=0;i<4;i++){
                int row = rbase + r0 + i;
                if (FWD){
                    g_lf[row*(2*Tt) + 2*t]   = l0[i];
                    g_lf[row*(2*Tt) + 2*t+1] = l1[i];
                } else {
                    float L0 = g_lf[row*(2*Tt)+2*t]   + l0[i] + bh0;
                    float L1 = g_lf[row*(2*Tt)+2*t+1] + l1[i] + bh1;
                    int gi = (row*Tt + t)*2;
                    float u0 = gum[gi], u1 = gum[gi+1];
                    float gg0 = -logf(-logf(u0+EPSg)+EPSg);
                    float gg1 = -logf(-logf(u1+EPSg)+EPSg);
                    float dlt = ((L1+gg1)-(L0+gg0)) * 100.0f;   // /TAU
                    g_hw[row*Tt+t] = 1.0f/(1.0f+__expf(-dlt));  // softmax[:,1]
                }
            }
        }
        __syncthreads();
    }
}

// =====================================================================
// K4: attention (scores, softmax, hard gating, weighted V) + final GRU cell
// block = 64 rows (4 batches), 256 threads
// =====================================================================
__global__ __launch_bounds__(256,1)
void k_attn_cell(const float* __restrict__ hidden,
                 const float* __restrict__ Wih_c, const float* __restrict__ Whh_c,
                 const float* __restrict__ bih_c, const float* __restrict__ bhh_c,
                 float* __restrict__ out)
{
    extern __shared__ float sm[];
    float* qs  = sm;                 // 64*65
    float* ks_ = qs  + 64*65;
    float* vs  = ks_ + 64*65;
    float* xs  = vs  + 64*65;
    float* hds = xs  + 64*65;
    float* Wi  = hds + 64*65;        // 64*196 : Wi[d][g] = Wih_c[g][d]
    float* Wh  = Wi  + 64*196;
    float* hw  = Wh  + 64*196;       // 64*16
    float* sc  = hw  + 64*16;        // 64*16
    const int tid = threadIdx.x;
    const int rbase = blockIdx.x * 64;

    for (int idx=tid; idx<4096; idx+=256){
        int r=idx>>6, d=idx&63;
        qs [r*65+d]=g_q[(rbase+r)*64+d];
        ks_[r*65+d]=g_k[(rbase+r)*64+d];
        vs [r*65+d]=g_v[(rbase+r)*64+d];
        hds[r*65+d]=hidden[(rbase+r)*64+d];
    }
    for (int idx=tid; idx<192*64; idx+=256){
        int g=idx>>6, d=idx&63;
        Wi[d*196+g]=Wih_c[idx];
        Wh[d*196+g]=Whh_c[idx];
    }
    for (int idx=tid; idx<64*Tt; idx+=256){
        int r=idx/Tt, t=idx-r*Tt;
        hw[r*16+t]=g_hw[(rbase+r)*Tt+t];
    }
    __syncthreads();

    {   // scores: 4 threads per row, 4 t's each
        int rp = tid>>2, qq = tid&3;
        #pragma unroll
        for (int s2=0; s2<4; ++s2){
            int t = qq*4+s2;
            if (t < Tt){
                int ii = rp & 15;
                int jl = (rp & 48) + t + (t>=ii ? 1 : 0);
                float dot=0.f;
                #pragma unroll 8
                for (int d=0; d<64; ++d) dot += qs[rp*65+d]*ks_[jl*65+d];
                sc[rp*16+t] = dot*0.125f;      // / sqrt(64)
            }
        }
    }
    __syncthreads();
    if (tid < 64){
        int r=tid;
        float m=-1e30f;
        #pragma unroll
        for (int t=0;t<Tt;t++) m = fmaxf(m, sc[r*16+t]);
        float e[Tt]; float ssum=0.f;
        #pragma unroll
        for (int t=0;t<Tt;t++){ e[t]=__expf(sc[r*16+t]-m); ssum+=e[t]; }
        float inv = 1.0f/ssum;
        #pragma unroll
        for (int t=0;t<Tt;t++) sc[r*16+t] = e[t]*inv*hw[r*16+t];  // soft * hard_w
    }
    __syncthreads();
    for (int idx=tid; idx<4096; idx+=256){
        int r=idx>>6, d=idx&63;
        int ii = r & 15, rb2 = r & 48;
        float x=0.f;
        #pragma unroll
        for (int t=0;t<Tt;t++){
            int jl = rb2 + t + (t>=ii ? 1 : 0);
            x += vs[jl*65+d]*sc[r*16+t];
        }
        xs[r*65+d]=x;
    }
    __syncthreads();

    // final GRU cell
    const int ty=tid>>4, tx=tid&15; const int r0=ty*4;
    float brz0[4], brz1[4], bni[4], bnh[4];
    #pragma unroll
    for (int k=0;k<4;k++){
        int d = tx+16*k;
        brz0[k]=bih_c[d]     + bhh_c[d];
        brz1[k]=bih_c[d+64]  + bhh_c[d+64];
        bni[k] =bih_c[d+128];
        bnh[k] =bhh_c[d+128];
    }
    float arz0[4][4], arz1[4][4], ain[4][4], ahn[4][4];
    #pragma unroll
    for (int i=0;i<4;i++)
        #pragma unroll
        for (int k=0;k<4;k++){ arz0[i][k]=0.f; arz1[i][k]=0.f; ain[i][k]=0.f; ahn[i][k]=0.f; }

    for (int dd=0; dd<64; ++dd){
        float ax[4], ah[4];
        #pragma unroll
        for (int i=0;i<4;i++){ ax[i]=xs[(r0+i)*65+dd]; ah[i]=hds[(r0+i)*65+dd]; }
        #pragma unroll
        for (int k=0;k<4;k++){
            int c = tx+16*k;
            float wir=Wi[dd*196+c], wiz=Wi[dd*196+c+64], win=Wi[dd*196+c+128];
            float whr=Wh[dd*196+c], whz=Wh[dd*196+c+64], whn=Wh[dd*196+c+128];
            #pragma unroll
            for (int i=0;i<4;i++){
                arz0[i][k] += ax[i]*wir + ah[i]*whr;
                arz1[i][k] += ax[i]*wiz + ah[i]*whz;
                ain [i][k] += ax[i]*win;
                ahn [i][k] += ah[i]*whn;
            }
        }
    }
    #pragma unroll
    for (int i=0;i<4;i++){
        int rl=r0+i;
        #pragma unroll
        for (int k=0;k<4;k++){
            int d = tx+16*k;
            float r = sigm(arz0[i][k] + brz0[k]);
            float z = sigm(arz1[i][k] + brz1[k]);
            float n = tanh_(ain[i][k] + bni[k] + r*(ahn[i][k] + bnh[k]));
            float ho = hds[rl*65+d];
            out[(rbase+rl)*64 + d] = (1.0f-z)*n + z*ho;
        }
    }
}

// =====================================================================
extern "C" void kernel_launch(void* const* d_in, const int* in_sizes, int n_in,
                              void* d_out, int out_size)
{
    (void)in_sizes; (void)n_in; (void)out_size;
    const float* obs    = (const float*)d_in[0];
    const float* hidden = (const float*)d_in[1];
    const float* gum    = (const float*)d_in[2];
    const float* W_enc  = (const float*)d_in[3];
    const float* b_enc  = (const float*)d_in[4];
    const float* Wih_f  = (const float*)d_in[5];
    const float* Whh_f  = (const float*)d_in[6];
    const float* bih_f  = (const float*)d_in[7];
    const float* bhh_f  = (const float*)d_in[8];
    const float* Wih_b  = (const float*)d_in[9];
    const float* Whh_b  = (const float*)d_in[10];
    const float* bih_b  = (const float*)d_in[11];
    const float* bhh_b  = (const float*)d_in[12];
    const float* W_hard = (const float*)d_in[13];
    const float* b_hard = (const float*)d_in[14];
    const float* Wq     = (const float*)d_in[15];
    const float* Wk     = (const float*)d_in[16];
    const float* Wv     = (const float*)d_in[17];
    const float* b_v    = (const float*)d_in[18];
    const float* Wih_c  = (const float*)d_in[19];
    const float* Whh_c  = (const float*)d_in[20];
    const float* bih_c  = (const float*)d_in[21];
    const float* bhh_c  = (const float*)d_in[22];
    float* out = (float*)d_out;

    const int sm1 = (3*64*65) * (int)sizeof(float);                        // 49,920 B
    const int sm2 = (3*64*196 + 64*65) * (int)sizeof(float);               // 167,168 B
    const int sm4 = (5*64*65 + 2*64*196 + 2*64*16) * (int)sizeof(float);   // 191,744 B

    cudaFuncSetAttribute(k_proj,      cudaFuncAttributeMaxDynamicSharedMemorySize, sm1);
    cudaFuncSetAttribute(k_gru<1>,    cudaFuncAttributeMaxDynamicSharedMemorySize, sm2);
    cudaFuncSetAttribute(k_gru<0>,    cudaFuncAttributeMaxDynamicSharedMemorySize, sm2);
    cudaFuncSetAttribute(k_attn_cell, cudaFuncAttributeMaxDynamicSharedMemorySize, sm4);

    k_proj<<<256, 256, sm1>>>(obs, W_enc, b_enc, Wq, Wk, Wv, b_v,
                              Wih_f, bih_f, Wih_b, bih_b);
    k_gru<1><<<256, 256, sm2>>>(Whh_f, bhh_f, W_hard, b_hard, gum);
    k_gru<0><<<256, 256, sm2>>>(Whh_b, bhh_b, W_hard, b_hard, gum);
    k_attn_cell<<<256, 256, sm4>>>(hidden, Wih_c, Whh_c, bih_c, bhh_c, out);
}

// round 3
// speedup vs baseline: 1.0749x; 1.0749x over previous
#include <cuda_runtime.h>
#include <math.h>

#define NROWS 16384
#define Tt 15
#define EPSg 1e-10f

typedef unsigned long long u64t;

// ---------------- scratch ----------------
__device__ float g_q[NROWS*64];
__device__ float g_k[NROWS*64];
__device__ float g_v[NROWS*64];
__device__ float g_Gf [NROWS*192];
__device__ float g_Cbf[NROWS*192];
__device__ float g_Gb [NROWS*192];
__device__ float g_Cbb[NROWS*192];
__device__ float g_lf[NROWS*2*Tt];
__device__ float g_lb[NROWS*2*Tt];

__device__ __forceinline__ float sigm(float x){ return 1.0f/(1.0f+__expf(-x)); }
__device__ __forceinline__ float tanh_(float x){ return 2.0f/(1.0f+__expf(-2.0f*x)) - 1.0f; }

__device__ __forceinline__ u64t pk(float x, float y){
    u64t r; asm("mov.b64 %0,{%1,%2};" : "=l"(r) : "f"(x), "f"(y)); return r;
}
__device__ __forceinline__ float2 up(u64t v){
    float2 r; asm("mov.b64 {%0,%1},%2;" : "=f"(r.x), "=f"(r.y) : "l"(v)); return r;
}
__device__ __forceinline__ void fma2(u64t& d, u64t a, u64t b){
    asm("fma.rn.f32x2 %0,%1,%2,%0;" : "+l"(d) : "l"(a), "l"(b));
}

// paired weight position: float index for W^T[d][c] in column-pair layout
// pair p=(c>>5)&1 holds cols (32p+tx, 32p+16+tx); half h=(c>>4)&1
__device__ __forceinline__ int pairpos64(int d, int c){
    return ((d<<5) + (((c>>5)&1)<<4) + (c&15))*2 + ((c>>4)&1);
}

// =====================================================================
// K1: encoder + all input projections. 256 thr, 64 rows/block, f32x2.
// smem: Os(64*68) Hs(64*68) Wt(4096 paired)
// =====================================================================
__global__ __launch_bounds__(256)
void k_proj(const float* __restrict__ obs,
            const float* __restrict__ W_enc, const float* __restrict__ b_enc,
            const float* __restrict__ Wq, const float* __restrict__ Wk,
            const float* __restrict__ Wv, const float* __restrict__ b_v,
            const float* __restrict__ Wih_f, const float* __restrict__ bih_f,
            const float* __restrict__ Wih_b, const float* __restrict__ bih_b)
{
    extern __shared__ float sm[];
    float* Os = sm;                 // 64*68
    float* Hs = sm + 64*68;         // 64*68
    float* Wt = sm + 2*64*68;       // 4096 (paired)
    const u64t* Wt64 = (const u64t*)Wt;
    const int tid = threadIdx.x;
    const int rbase = blockIdx.x * 64;
    const int ty = tid >> 4, tx = tid & 15;
    const int r0 = ty * 4;
    int dcol[4];
    #pragma unroll
    for (int k=0;k<4;k++) dcol[k] = tx + ((k>>1)<<5) + ((k&1)<<4);

    for (int idx = tid; idx < 4096; idx += 256) {
        int r = idx >> 6, c = idx & 63;
        Os[r*68+c] = obs[(rbase+r)*64 + c];
        Wt[pairpos64(r, c)] = W_enc[idx];        // W_enc[d*64+c]
    }
    __syncthreads();

    {   // h_enc = relu(obs @ W_enc + b)
        u64t acc[4][2];
        #pragma unroll
        for (int i=0;i<4;i++){ acc[i][0]=0ull; acc[i][1]=0ull; }
        for (int dd=0; dd<64; ++dd){
            u64t pa[4];
            #pragma unroll
            for (int i=0;i<4;i++){ float a=Os[(r0+i)*68+dd]; pa[i]=pk(a,a); }
            #pragma unroll
            for (int p=0;p<2;p++){
                u64t w = Wt64[dd*32 + p*16 + tx];
                #pragma unroll
                for (int i=0;i<4;i++) fma2(acc[i][p], pa[i], w);
            }
        }
        #pragma unroll
        for (int i=0;i<4;i++)
            #pragma unroll
            for (int p=0;p<2;p++){
                float2 v = up(acc[i][p]);
                int d0 = dcol[2*p], d1 = dcol[2*p+1];
                Hs[(r0+i)*68+d0] = fmaxf(v.x + b_enc[d0], 0.0f);
                Hs[(r0+i)*68+d1] = fmaxf(v.y + b_enc[d1], 0.0f);
            }
    }
    __syncthreads();

    for (int s = 0; s < 15; ++s){
        const float* Wsrc; const float* bias=nullptr; int mode; int stride; int colBase=0; float* dst; int doRelu=0;
        if      (s==0){ Wsrc=Wq;    dst=g_q;   stride=64;  mode=0; }
        else if (s==1){ Wsrc=Wk;    dst=g_k;   stride=64;  mode=0; }
        else if (s==2){ Wsrc=Wv;    dst=g_v;   stride=64;  mode=0; bias=b_v; doRelu=1; }
        else if (s<6 ){ Wsrc=Wih_f; dst=g_Cbf; stride=192; colBase=(s-3 )*64; mode=1; bias=bih_f; }
        else if (s<9 ){ Wsrc=Wih_f; dst=g_Gf;  stride=192; colBase=(s-6 )*64; mode=2; }
        else if (s<12){ Wsrc=Wih_b; dst=g_Cbb; stride=192; colBase=(s-9 )*64; mode=1; bias=bih_b; }
        else          { Wsrc=Wih_b; dst=g_Gb;  stride=192; colBase=(s-12)*64; mode=2; }

        for (int idx = tid; idx < 4096; idx += 256){
            int hi = idx >> 6, lo = idx & 63;
            if (mode==0) Wt[pairpos64(hi, lo)] = Wsrc[idx];               // W[d*64+c] : hi=d,lo=c
            else {
                int off = (colBase+hi)*128 + lo + (mode==2 ? 64 : 0);     // hi=c(gate), lo=d
                Wt[pairpos64(lo, hi)] = Wsrc[off];
            }
        }
        __syncthreads();

        u64t acc[4][2];
        #pragma unroll
        for (int i=0;i<4;i++){ acc[i][0]=0ull; acc[i][1]=0ull; }
        for (int dd=0; dd<64; ++dd){
            u64t pa[4];
            #pragma unroll
            for (int i=0;i<4;i++){ float a=Hs[(r0+i)*68+dd]; pa[i]=pk(a,a); }
            #pragma unroll
            for (int p=0;p<2;p++){
                u64t w = Wt64[dd*32 + p*16 + tx];
                #pragma unroll
                for (int i=0;i<4;i++) fma2(acc[i][p], pa[i], w);
            }
        }
        #pragma unroll
        for (int i=0;i<4;i++)
            #pragma unroll
            for (int p=0;p<2;p++){
                float2 v = up(acc[i][p]);
                #pragma unroll
                for (int h=0;h<2;h++){
                    int d = dcol[2*p+h];
                    float vv = (h ? v.y : v.x) + (bias ? bias[colBase+d] : 0.0f);
                    if (doRelu) vv = fmaxf(vv, 0.0f);
                    dst[(rbase+r0+i)*stride + colBase + d] = vv;
                }
            }
        __syncthreads();
    }
}

// =====================================================================
// K2: both GRU directions in one launch. 512 blocks, 512 threads.
// blockIdx < 256 -> forward, else backward. 2 rows/thread, f32x2.
// smem: Gs(64*200) Cbs(64*200) Wp(12288 paired) hs(64*72)
// =====================================================================
__global__ __launch_bounds__(512,1)
void k_gru(const float* __restrict__ Whh_f, const float* __restrict__ bhh_f,
           const float* __restrict__ Whh_b, const float* __restrict__ bhh_b,
           const float* __restrict__ W_hard)
{
    extern __shared__ float sm[];
    float* Gs  = sm;                  // 64*200
    float* Cbs = sm + 64*200;         // 64*200
    float* Wp  = sm + 2*64*200;       // 12288 floats (paired, per-dd stride 192)
    float* hs  = sm + 2*64*200 + 12288; // 64*72
    const u64t* Wp64 = (const u64t*)Wp;
    const int tid = threadIdx.x;
    const int fwd = (blockIdx.x < 256);
    const int rbase = (blockIdx.x & 255) * 64;
    const int ty = tid >> 4, tx = tid & 15;
    const int r0 = ty*2;
    const float* Gsrc  = fwd ? g_Gf  : g_Gb;
    const float* Cbsrc = fwd ? g_Cbf : g_Cbb;
    const float* Whh   = fwd ? Whh_f : Whh_b;
    const float* bhh   = fwd ? bhh_f : bhh_b;
    float* lout = fwd ? g_lf : g_lb;

    int dcol[4];
    #pragma unroll
    for (int k=0;k<4;k++) dcol[k] = tx + ((k>>1)<<5) + ((k&1)<<4);

    for (int idx = tid; idx < 64*192; idx += 512){
        int r = idx / 192, g = idx - r*192;
        Gs [r*200+g] = Gsrc [(rbase+r)*192+g];
        Cbs[r*200+g] = Cbsrc[(rbase+r)*192+g];
    }
    for (int idx = tid; idx < 192*64; idx += 512){
        int g = idx >> 6, d = idx & 63;
        int gate = g >> 6, rem = g & 63;
        int pair = (rem>>5)&1, h = (rem>>4)&1, txx = rem&15;
        Wp[(d*96 + (gate*2+pair)*16 + txx)*2 + h] = Whh[idx];
    }
    for (int idx = tid; idx < 64*72; idx += 512) hs[idx] = 0.0f;

    float brk[4], bzk[4], bnk[4], w0k[4], w1k[4];
    #pragma unroll
    for (int k=0;k<4;k++){
        int d = dcol[k];
        brk[k]=bhh[d]; bzk[k]=bhh[d+64]; bnk[k]=bhh[d+128];
        int wr = fwd ? d : (64+d);
        w0k[k]=W_hard[wr*2]; w1k[k]=W_hard[wr*2+1];
    }
    __syncthreads();

    for (int step=0; step<Tt; ++step){
        const int t = fwd ? step : (Tt-1-step);
        u64t acc[2][6];
        #pragma unroll
        for (int i=0;i<2;i++)
            #pragma unroll
            for (int gp=0;gp<6;gp++) acc[i][gp]=0ull;

        #pragma unroll 2
        for (int dd=0; dd<64; ++dd){
            float a0 = hs[r0*72+dd], a1 = hs[(r0+1)*72+dd];
            u64t pa0 = pk(a0,a0), pa1 = pk(a1,a1);
            const u64t* wrow = Wp64 + dd*96 + tx;
            #pragma unroll
            for (int gp=0; gp<6; gp++){
                u64t w = wrow[gp*16];
                fma2(acc[0][gp], pa0, w);
                fma2(acc[1][gp], pa1, w);
            }
        }

        float ga[2][3][4];
        #pragma unroll
        for (int i=0;i<2;i++)
            #pragma unroll
            for (int g=0;g<3;g++)
                #pragma unroll
                for (int p=0;p<2;p++){
                    float2 v = up(acc[i][g*2+p]);
                    ga[i][g][2*p]=v.x; ga[i][g][2*p+1]=v.y;
                }

        float hnew[2][4], l0[2], l1[2];
        #pragma unroll
        for (int i=0;i<2;i++){ l0[i]=0.f; l1[i]=0.f; }
        #pragma unroll
        for (int i=0;i<2;i++){
            int rl = r0+i;
            int ii = rl & 15;
            int jl = (rl & 48) + t + (t>=ii ? 1 : 0);
            #pragma unroll
            for (int k=0;k<4;k++){
                int d = dcol[k];
                float ir  = Cbs[rl*200+d]     + Gs[jl*200+d];
                float iz  = Cbs[rl*200+d+64]  + Gs[jl*200+d+64];
                float inn = Cbs[rl*200+d+128] + Gs[jl*200+d+128];
                float r = sigm(ir + ga[i][0][k] + brk[k]);
                float z = sigm(iz + ga[i][1][k] + bzk[k]);
                float n = tanh_(inn + r*(ga[i][2][k] + bnk[k]));
                float ho = hs[rl*72+d];
                float hv = (1.0f - z)*n + z*ho;
                hnew[i][k] = hv;
                l0[i] += hv * w0k[k];
                l1[i] += hv * w1k[k];
            }
        }
        __syncthreads();
        #pragma unroll
        for (int i=0;i<2;i++)
            #pragma unroll
            for (int k=0;k<4;k++)
                hs[(r0+i)*72 + dcol[k]] = hnew[i][k];

        #pragma unroll
        for (int off=8; off>=1; off>>=1){
            #pragma unroll
            for (int i=0;i<2;i++){
                l0[i] += __shfl_xor_sync(0xffffffffu, l0[i], off);
                l1[i] += __shfl_xor_sync(0xffffffffu, l1[i], off);
            }
        }
        if (tx == 0){
            #pragma unroll
            for (int i=0;i<2;i++){
                int row = rbase + r0 + i;
                lout[row*(2*Tt) + 2*t]   = l0[i];
                lout[row*(2*Tt) + 2*t+1] = l1[i];
            }
        }
        __syncthreads();
    }
}

// =====================================================================
// K3: gumbel hard weights + attention + final GRU cell. 512 threads.
// =====================================================================
__global__ __launch_bounds__(512,1)
void k_attn_cell(const float* __restrict__ hidden,
                 const float* __restrict__ gum,
                 const float* __restrict__ b_hard,
                 const float* __restrict__ Wih_c, const float* __restrict__ Whh_c,
                 const float* __restrict__ bih_c, const float* __restrict__ bhh_c,
                 float* __restrict__ out)
{
    extern __shared__ float sm[];
    float* qs  = sm;                 // 64*65
    float* ks_ = qs  + 64*65;
    float* vs  = ks_ + 64*65;
    float* xs  = vs  + 64*65;
    float* hds = xs  + 64*65;
    float* Wi  = hds + 64*65;        // 12288 paired
    float* Wh  = Wi  + 12288;        // 12288 paired
    float* hw  = Wh  + 12288;        // 64*16
    float* sc  = hw  + 64*16;        // 64*16
    const u64t* Wi64 = (const u64t*)Wi;
    const u64t* Wh64 = (const u64t*)Wh;
    const int tid = threadIdx.x;
    const int rbase = blockIdx.x * 64;

    for (int idx=tid; idx<4096; idx+=512){
        int r=idx>>6, d=idx&63;
        qs [r*65+d]=g_q[(rbase+r)*64+d];
        ks_[r*65+d]=g_k[(rbase+r)*64+d];
        vs [r*65+d]=g_v[(rbase+r)*64+d];
        hds[r*65+d]=hidden[(rbase+r)*64+d];
    }
    for (int idx=tid; idx<192*64; idx+=512){
        int g=idx>>6, d=idx&63;
        int gate=g>>6, rem=g&63;
        int pair=(rem>>5)&1, h=(rem>>4)&1, txx=rem&15;
        int pos = (d*96 + (gate*2+pair)*16 + txx)*2 + h;
        Wi[pos]=Wih_c[idx];
        Wh[pos]=Whh_c[idx];
    }
    {   // gumbel hard weights
        const float bh0 = b_hard[0], bh1 = b_hard[1];
        for (int idx=tid; idx<64*Tt; idx+=512){
            int r=idx/Tt, t=idx-r*Tt;
            int row = rbase + r;
            float L0 = g_lf[row*(2*Tt)+2*t]   + g_lb[row*(2*Tt)+2*t]   + bh0;
            float L1 = g_lf[row*(2*Tt)+2*t+1] + g_lb[row*(2*Tt)+2*t+1] + bh1;
            int gi = (row*Tt + t)*2;
            float u0 = gum[gi], u1 = gum[gi+1];
            float gg0 = -logf(-logf(u0+EPSg)+EPSg);
            float gg1 = -logf(-logf(u1+EPSg)+EPSg);
            float dlt = ((L1+gg1)-(L0+gg0)) * 100.0f;   // /TAU
            hw[r*16+t] = 1.0f/(1.0f+__expf(-dlt));
        }
    }
    __syncthreads();

    {   // scores: 8 threads/row, 2 t's each
        int rp = tid>>3, qq = tid&7;
        #pragma unroll
        for (int s2=0; s2<2; ++s2){
            int t = qq + 8*s2;
            if (t < Tt){
                int ii = rp & 15;
                int jl = (rp & 48) + t + (t>=ii ? 1 : 0);
                float dot=0.f;
                #pragma unroll 8
                for (int d=0; d<64; ++d) dot += qs[rp*65+d]*ks_[jl*65+d];
                sc[rp*16+t] = dot*0.125f;
            }
        }
    }
    __syncthreads();
    if (tid < 64){
        int r=tid;
        float m=-1e30f;
        #pragma unroll
        for (int t=0;t<Tt;t++) m = fmaxf(m, sc[r*16+t]);
        float e[Tt]; float ssum=0.f;
        #pragma unroll
        for (int t=0;t<Tt;t++){ e[t]=__expf(sc[r*16+t]-m); ssum+=e[t]; }
        float inv = 1.0f/ssum;
        #pragma unroll
        for (int t=0;t<Tt;t++) sc[r*16+t] = e[t]*inv*hw[r*16+t];
    }
    __syncthreads();
    for (int idx=tid; idx<4096; idx+=512){
        int r=idx>>6, d=idx&63;
        int ii = r & 15, rb2 = r & 48;
        float x=0.f;
        #pragma unroll
        for (int t=0;t<Tt;t++){
            int jl = rb2 + t + (t>=ii ? 1 : 0);
            x += vs[jl*65+d]*sc[r*16+t];
        }
        xs[r*65+d]=x;
    }
    __syncthreads();

    // final GRU cell: 2 rows/thread, f32x2
    const int ty=tid>>4, tx=tid&15; const int r0=ty*2;
    int dcol[4];
    #pragma unroll
    for (int k=0;k<4;k++) dcol[k] = tx + ((k>>1)<<5) + ((k&1)<<4);

    u64t arz0[2][2], arz1[2][2], ain[2][2], ahn[2][2];
    #pragma unroll
    for (int i=0;i<2;i++)
        #pragma unroll
        for (int p=0;p<2;p++){ arz0[i][p]=0ull; arz1[i][p]=0ull; ain[i][p]=0ull; ahn[i][p]=0ull; }

    #pragma unroll 2
    for (int dd=0; dd<64; ++dd){
        u64t pax[2], pah[2];
        #pragma unroll
        for (int i=0;i<2;i++){
            float ax=xs[(r0+i)*65+dd], ah=hds[(r0+i)*65+dd];
            pax[i]=pk(ax,ax); pah[i]=pk(ah,ah);
        }
        const u64t* wi = Wi64 + dd*96 + tx;
        const u64t* wh = Wh64 + dd*96 + tx;
        #pragma unroll
        for (int p=0;p<2;p++){
            u64t wir=wi[p*16], wiz=wi[(2+p)*16], win=wi[(4+p)*16];
            u64t whr=wh[p*16], whz=wh[(2+p)*16], whn=wh[(4+p)*16];
            #pragma unroll
            for (int i=0;i<2;i++){
                fma2(arz0[i][p], pax[i], wir); fma2(arz0[i][p], pah[i], whr);
                fma2(arz1[i][p], pax[i], wiz); fma2(arz1[i][p], pah[i], whz);
                fma2(ain [i][p], pax[i], win);
                fma2(ahn [i][p], pah[i], whn);
            }
        }
    }
    #pragma unroll
    for (int i=0;i<2;i++){
        int rl=r0+i;
        #pragma unroll
        for (int p=0;p<2;p++){
            float2 vrz0=up(arz0[i][p]), vrz1=up(arz1[i][p]), vin=up(ain[i][p]), vhn=up(ahn[i][p]);
            #pragma unroll
            for (int h=0;h<2;h++){
                int d = dcol[2*p+h];
                float a0 = h? vrz0.y : vrz0.x;
                float a1 = h? vrz1.y : vrz1.x;
                float a2 = h? vin.y  : vin.x;
                float a3 = h? vhn.y  : vhn.x;
                float r = sigm(a0 + bih_c[d]     + bhh_c[d]);
                float z = sigm(a1 + bih_c[d+64]  + bhh_c[d+64]);
                float n = tanh_(a2 + bih_c[d+128] + r*(a3 + bhh_c[d+128]));
                float ho = hds[rl*65+d];
                out[(rbase+rl)*64 + d] = (1.0f-z)*n + z*ho;
            }
        }
    }
}

// =====================================================================
extern "C" void kernel_launch(void* const* d_in, const int* in_sizes, int n_in,
                              void* d_out, int out_size)
{
    (void)in_sizes; (void)n_in; (void)out_size;
    const float* obs    = (const float*)d_in[0];
    const float* hidden = (const float*)d_in[1];
    const float* gum    = (const float*)d_in[2];
    const float* W_enc  = (const float*)d_in[3];
    const float* b_enc  = (const float*)d_in[4];
    const float* Wih_f  = (const float*)d_in[5];
    const float* Whh_f  = (const float*)d_in[6];
    const float* bih_f  = (const float*)d_in[7];
    const float* bhh_f  = (const float*)d_in[8];
    const float* Wih_b  = (const float*)d_in[9];
    const float* Whh_b  = (const float*)d_in[10];
    const float* bih_b  = (const float*)d_in[11];
    const float* bhh_b  = (const float*)d_in[12];
    const float* W_hard = (const float*)d_in[13];
    const float* b_hard = (const float*)d_in[14];
    const float* Wq     = (const float*)d_in[15];
    const float* Wk     = (const float*)d_in[16];
    const float* Wv     = (const float*)d_in[17];
    const float* b_v    = (const float*)d_in[18];
    const float* Wih_c  = (const float*)d_in[19];
    const float* Whh_c  = (const float*)d_in[20];
    const float* bih_c  = (const float*)d_in[21];
    const float* bhh_c  = (const float*)d_in[22];
    float* out = (float*)d_out;

    const int sm1 = (2*64*68 + 4096) * (int)sizeof(float);                  // 51,200 B
    const int sm2 = (2*64*200 + 12288 + 64*72) * (int)sizeof(float);        // 169,984 B
    const int sm4 = (5*64*65 + 2*12288 + 2*64*16) * (int)sizeof(float);     // 189,696 B

    cudaFuncSetAttribute(k_proj,      cudaFuncAttributeMaxDynamicSharedMemorySize, sm1);
    cudaFuncSetAttribute(k_gru,       cudaFuncAttributeMaxDynamicSharedMemorySize, sm2);
    cudaFuncSetAttribute(k_attn_cell, cudaFuncAttributeMaxDynamicSharedMemorySize, sm4);

    k_proj<<<256, 256, sm1>>>(obs, W_enc, b_enc, Wq, Wk, Wv, b_v,
                              Wih_f, bih_f, Wih_b, bih_b);
    k_gru<<<512, 512, sm2>>>(Whh_f, bhh_f, Whh_b, bhh_b, W_hard);
    k_attn_cell<<<256, 512, sm4>>>(hidden, gum, b_hard,
                                   Wih_c, Whh_c, bih_c, bhh_c, out);
}

// round 5
// speedup vs baseline: 1.1145x; 1.0368x over previous
#include <cuda_runtime.h>
#include <math.h>

#define NROWS 16384
#define Tt 15
#define EPSg 1e-10f

typedef unsigned long long u64t;

// ---------------- scratch ----------------
__device__ float g_h[NROWS*64];
__device__ float g_q[NROWS*64];
__device__ float g_k[NROWS*64];
__device__ float g_v[NROWS*64];
// paired layout: [row][ (gate*32+c)*2 + h ]  value = X[row][gate*64 + c + 32*h]
__device__ float g_Gf [NROWS*192];
__device__ float g_Cbf[NROWS*192];
__device__ float g_Gb [NROWS*192];
__device__ float g_Cbb[NROWS*192];
__device__ float g_lf[NROWS*2*Tt];
__device__ float g_lb[NROWS*2*Tt];

__device__ __forceinline__ float sigm(float x){ return 1.0f/(1.0f+__expf(-x)); }
__device__ __forceinline__ float tanh_(float x){ return 2.0f/(1.0f+__expf(-2.0f*x)) - 1.0f; }

__device__ __forceinline__ u64t pk(float x, float y){
    u64t r; asm("mov.b64 %0,{%1,%2};" : "=l"(r) : "f"(x), "f"(y)); return r;
}
__device__ __forceinline__ float2 up(u64t v){
    float2 r; asm("mov.b64 {%0,%1},%2;" : "=f"(r.x), "=f"(r.y) : "l"(v)); return r;
}
__device__ __forceinline__ void fma2(u64t& d, u64t a, u64t b){
    asm("fma.rn.f32x2 %0,%1,%2,%0;" : "+l"(d) : "l"(a), "l"(b));
}
__device__ __forceinline__ u64t add2_(u64t a, u64t b){
    u64t r; asm("add.rn.f32x2 %0,%1,%2;" : "=l"(r) : "l"(a), "l"(b)); return r;
}

// pairpos for proj micro-kernel weight tiles (16-lane pairing)
__device__ __forceinline__ int pairpos64(int d, int c){
    return ((d<<5) + (((c>>5)&1)<<4) + (c&15))*2 + ((c>>4)&1);
}

// =====================================================================
// K0: encoder. h_enc = relu(obs @ W_enc + b_enc) -> g_h
// =====================================================================
__global__ __launch_bounds__(256)
void k_enc(const float* __restrict__ obs,
           const float* __restrict__ W_enc, const float* __restrict__ b_enc)
{
    extern __shared__ float sm[];
    float* Os = sm;                 // 64*68
    float* Wt = sm + 64*68;         // 4096 paired
    const u64t* Wt64 = (const u64t*)Wt;
    const int tid = threadIdx.x;
    const int rbase = blockIdx.x * 64;
    const int ty = tid >> 4, tx = tid & 15;
    const int r0 = ty * 4;
    int dcol[4];
    #pragma unroll
    for (int k=0;k<4;k++) dcol[k] = tx + ((k>>1)<<5) + ((k&1)<<4);

    for (int idx = tid; idx < 4096; idx += 256) {
        int r = idx >> 6, c = idx & 63;
        Os[r*68+c] = obs[(rbase+r)*64 + c];
        Wt[pairpos64(r, c)] = W_enc[idx];
    }
    __syncthreads();

    u64t acc[4][2];
    #pragma unroll
    for (int i=0;i<4;i++){ acc[i][0]=0ull; acc[i][1]=0ull; }
    for (int dd=0; dd<64; ++dd){
        u64t pa[4];
        #pragma unroll
        for (int i=0;i<4;i++){ float a=Os[(r0+i)*68+dd]; pa[i]=pk(a,a); }
        #pragma unroll
        for (int p=0;p<2;p++){
            u64t w = Wt64[dd*32 + p*16 + tx];
            #pragma unroll
            for (int i=0;i<4;i++) fma2(acc[i][p], pa[i], w);
        }
    }
    #pragma unroll
    for (int i=0;i<4;i++)
        #pragma unroll
        for (int p=0;p<2;p++){
            float2 v = up(acc[i][p]);
            int d0 = dcol[2*p], d1 = dcol[2*p+1];
            g_h[(rbase+r0+i)*64 + d0] = fmaxf(v.x + b_enc[d0], 0.0f);
            g_h[(rbase+r0+i)*64 + d1] = fmaxf(v.y + b_enc[d1], 0.0f);
        }
}

// =====================================================================
// K1: projections. grid (256 tiles, 5 groups), 3 segments per block.
// =====================================================================
__global__ __launch_bounds__(256)
void k_proj2(const float* __restrict__ Wq, const float* __restrict__ Wk,
             const float* __restrict__ Wv, const float* __restrict__ b_v,
             const float* __restrict__ Wih_f, const float* __restrict__ bih_f,
             const float* __restrict__ Wih_b, const float* __restrict__ bih_b)
{
    extern __shared__ float sm[];
    float* Hs = sm;                 // 64*68
    float* Wt = sm + 64*68;         // 4096 paired
    const u64t* Wt64 = (const u64t*)Wt;
    const int tid = threadIdx.x;
    const int rbase = blockIdx.x * 64;
    const int gy = blockIdx.y;
    const int ty = tid >> 4, tx = tid & 15;
    const int r0 = ty * 4;
    int dcol[4];
    #pragma unroll
    for (int k=0;k<4;k++) dcol[k] = tx + ((k>>1)<<5) + ((k&1)<<4);

    for (int idx = tid; idx < 4096; idx += 256) {
        int r = idx >> 6, c = idx & 63;
        Hs[r*68+c] = g_h[(rbase+r)*64 + c];
    }

    for (int j = 0; j < 3; ++j){
        const float* Wsrc=nullptr; const float* bias=nullptr;
        float* dst=nullptr; int mode; int doRelu=0; int gate=j;
        if (gy==0){
            mode=0;
            if (j==0){ Wsrc=Wq; dst=g_q; }
            else if (j==1){ Wsrc=Wk; dst=g_k; }
            else { Wsrc=Wv; dst=g_v; bias=b_v; doRelu=1; }
        } else if (gy==1){ mode=1; Wsrc=Wih_f; dst=g_Cbf; bias=bih_f; }
        else if   (gy==2){ mode=2; Wsrc=Wih_f; dst=g_Gf; }
        else if   (gy==3){ mode=1; Wsrc=Wih_b; dst=g_Cbb; bias=bih_b; }
        else              { mode=2; Wsrc=Wih_b; dst=g_Gb; }
        const int colBase = gate*64;

        __syncthreads();
        for (int idx = tid; idx < 4096; idx += 256){
            int hi = idx >> 6, lo = idx & 63;
            if (mode==0) Wt[pairpos64(hi, lo)] = Wsrc[idx];
            else {
                int off = (colBase+hi)*128 + lo + (mode==2 ? 64 : 0);
                Wt[pairpos64(lo, hi)] = Wsrc[off];
            }
        }
        __syncthreads();

        u64t acc[4][2];
        #pragma unroll
        for (int i=0;i<4;i++){ acc[i][0]=0ull; acc[i][1]=0ull; }
        for (int dd=0; dd<64; ++dd){
            u64t pa[4];
            #pragma unroll
            for (int i=0;i<4;i++){ float a=Hs[(r0+i)*68+dd]; pa[i]=pk(a,a); }
            #pragma unroll
            for (int p=0;p<2;p++){
                u64t w = Wt64[dd*32 + p*16 + tx];
                #pragma unroll
                for (int i=0;i<4;i++) fma2(acc[i][p], pa[i], w);
            }
        }

        if (mode==0){
            #pragma unroll
            for (int i=0;i<4;i++)
                #pragma unroll
                for (int p=0;p<2;p++){
                    float2 v = up(acc[i][p]);
                    #pragma unroll
                    for (int h=0;h<2;h++){
                        int d = dcol[2*p+h];
                        float vv = (h ? v.y : v.x) + (bias ? bias[d] : 0.0f);
                        if (doRelu) vv = fmaxf(vv, 0.0f);
                        dst[(rbase+r0+i)*64 + d] = vv;
                    }
                }
        } else {
            float b0=0.f,b1=0.f,b2=0.f,b3=0.f;
            if (bias){
                b0=bias[colBase+tx]; b1=bias[colBase+tx+16];
                b2=bias[colBase+tx+32]; b3=bias[colBase+tx+48];
            }
            u64t* dst64 = (u64t*)dst;
            #pragma unroll
            for (int i=0;i<4;i++){
                float2 v0 = up(acc[i][0]);   // cols tx, tx+16
                float2 v1 = up(acc[i][1]);   // cols tx+32, tx+48
                int row = rbase + r0 + i;
                dst64[row*96 + gate*32 + tx]      = pk(v0.x + b0, v1.x + b2);
                dst64[row*96 + gate*32 + tx + 16] = pk(v0.y + b1, v1.y + b3);
            }
        }
    }
}

// =====================================================================
// K2: both GRU directions. 512 blocks x 256 threads.
// 8 warps/block; warp owns rows wid*8..+7; lane owns col pair (c, c+32).
// No __syncthreads in the step loop (hs rows are warp-private).
// smem: Wp 48K + hs2 33K + CbP 48K + GP 48K = 181,248 B
// =====================================================================
__global__ __launch_bounds__(256,1)
void k_gru(const float* __restrict__ Whh_f, const float* __restrict__ bhh_f,
           const float* __restrict__ Whh_b, const float* __restrict__ bhh_b,
           const float* __restrict__ W_hard)
{
    extern __shared__ float sm[];
    u64t*  Wp64  = (u64t*)sm;                     // 6144 u64
    float2* hs2  = (float2*)(sm + 12288);         // 64*66 float2
    u64t*  CbP64 = (u64t*)(sm + 12288 + 64*66*2); // 6144 u64
    u64t*  GP64  = CbP64 + 6144;                  // 6144 u64
    const int tid  = threadIdx.x;
    const int wid  = tid >> 5;
    const int lane = tid & 31;
    const int fwd = (blockIdx.x < 256);
    const int rbase = (blockIdx.x & 255) * 64;
    const int r0 = wid * 8;
    const float* Gsrc  = fwd ? g_Gf  : g_Gb;
    const float* Cbsrc = fwd ? g_Cbf : g_Cbb;
    const float* Whh   = fwd ? Whh_f : Whh_b;
    const float* bhh   = fwd ? bhh_f : bhh_b;
    float* lout = fwd ? g_lf : g_lb;

    // weights: Wp[(dd*3+g)*32 + c] = ( Whh[(g*64+c)*64+dd], Whh[(g*64+c+32)*64+dd] )
    for (int i = tid; i < 12288; i += 256){
        int gd = i >> 6, dd = i & 63;
        int g = gd >> 6, cc = gd & 63;
        int c = cc & 31, h = cc >> 5;
        ((float*)Wp64)[(((dd*3 + g)*32 + c) << 1) + h] = Whh[i];
    }
    {   // straight copies of paired G / Cb rows
        const float4* sG = (const float4*)(Gsrc  + (size_t)rbase*192);
        const float4* sC = (const float4*)(Cbsrc + (size_t)rbase*192);
        float4* dG = (float4*)GP64;
        float4* dC = (float4*)CbP64;
        for (int i = tid; i < 3072; i += 256){ dG[i] = sG[i]; dC[i] = sC[i]; }
    }
    for (int i = tid; i < 64*66; i += 256) hs2[i] = make_float2(0.f, 0.f);

    // per-lane constants
    float br_lo=bhh[lane],     br_hi=bhh[lane+32];
    float bz_lo=bhh[64+lane],  bz_hi=bhh[96+lane];
    float bn_lo=bhh[128+lane], bn_hi=bhh[160+lane];
    int wb = fwd ? 0 : 64;
    float w0_lo=W_hard[(wb+lane)*2],    w0_hi=W_hard[(wb+lane+32)*2];
    float w1_lo=W_hard[(wb+lane)*2+1],  w1_hi=W_hard[(wb+lane+32)*2+1];
    __syncthreads();

    for (int step=0; step<Tt; ++step){
        const int t = fwd ? step : (Tt-1-step);
        u64t acc[8][3];
        #pragma unroll
        for (int i=0;i<8;i++){ acc[i][0]=0ull; acc[i][1]=0ull; acc[i][2]=0ull; }

        if (step){
            #pragma unroll 2
            for (int dd=0; dd<64; dd+=2){
                u64t w00 = Wp64[(dd*3+0)*32 + lane];
                u64t w01 = Wp64[(dd*3+1)*32 + lane];
                u64t w02 = Wp64[(dd*3+2)*32 + lane];
                u64t w10 = Wp64[((dd+1)*3+0)*32 + lane];
                u64t w11 = Wp64[((dd+1)*3+1)*32 + lane];
                u64t w12 = Wp64[((dd+1)*3+2)*32 + lane];
                #pragma unroll
                for (int i=0;i<8;i++){
                    float4 av = *(const float4*)&hs2[(r0+i)*66 + dd]; // (a,a,a',a')
                    u64t pa0 = pk(av.x, av.y);
                    u64t pa1 = pk(av.z, av.w);
                    fma2(acc[i][0], pa0, w00);
                    fma2(acc[i][1], pa0, w01);
                    fma2(acc[i][2], pa0, w02);
                    fma2(acc[i][0], pa1, w10);
                    fma2(acc[i][1], pa1, w11);
                    fma2(acc[i][2], pa1, w12);
                }
            }
        }

        float l0[8], l1[8];
        #pragma unroll
        for (int i=0;i<8;i++){
            int rl = r0+i;
            int ii = rl & 15;
            int jl = (rl & 48) + t + (t>=ii ? 1 : 0);
            u64t gi0 = add2_(CbP64[rl*96      + lane], GP64[jl*96      + lane]);
            u64t gi1 = add2_(CbP64[rl*96 + 32 + lane], GP64[jl*96 + 32 + lane]);
            u64t gi2 = add2_(CbP64[rl*96 + 64 + lane], GP64[jl*96 + 64 + lane]);
            float2 v0=up(gi0), v1=up(gi1), v2=up(gi2);
            float2 a0=up(acc[i][0]), a1=up(acc[i][1]), a2=up(acc[i][2]);
            float ho_lo = hs2[rl*66 + lane].x;
            float ho_hi = hs2[rl*66 + 32 + lane].x;
            float r_lo = sigm(v0.x + a0.x + br_lo);
            float r_hi = sigm(v0.y + a0.y + br_hi);
            float z_lo = sigm(v1.x + a1.x + bz_lo);
            float z_hi = sigm(v1.y + a1.y + bz_hi);
            float n_lo = tanh_(v2.x + r_lo*(a2.x + bn_lo));
            float n_hi = tanh_(v2.y + r_hi*(a2.y + bn_hi));
            float hv_lo = (1.0f - z_lo)*n_lo + z_lo*ho_lo;
            float hv_hi = (1.0f - z_hi)*n_hi + z_hi*ho_hi;
            hs2[rl*66 + lane]      = make_float2(hv_lo, hv_lo);
            hs2[rl*66 + 32 + lane] = make_float2(hv_hi, hv_hi);
            l0[i] = hv_lo*w0_lo + hv_hi*w0_hi;
            l1[i] = hv_lo*w1_lo + hv_hi*w1_hi;
        }
        #pragma unroll
        for (int off=16; off>=1; off>>=1){
            #pragma unroll
            for (int i=0;i<8;i++){
                l0[i] += __shfl_xor_sync(0xffffffffu, l0[i], off);
                l1[i] += __shfl_xor_sync(0xffffffffu, l1[i], off);
            }
        }
        #pragma unroll
        for (int i=0;i<8;i++){
            if (lane == i){
                ((u64t*)lout)[(size_t)(rbase + r0 + i)*Tt + t] = pk(l0[i], l1[i]);
            }
        }
    }
}

// =====================================================================
// K3: gumbel hard weights + attention + final GRU cell. 512 threads.
// =====================================================================
__global__ __launch_bounds__(512,1)
void k_attn_cell(const float* __restrict__ hidden,
                 const float* __restrict__ gum,
                 const float* __restrict__ b_hard,
                 const float* __restrict__ Wih_c, const float* __restrict__ Whh_c,
                 const float* __restrict__ bih_c, const float* __restrict__ bhh_c,
                 float* __restrict__ out)
{
    extern __shared__ float sm[];
    float* qs  = sm;                 // 64*65
    float* ks_ = qs  + 64*65;
    float* vs  = ks_ + 64*65;
    float* xs  = vs  + 64*65;
    float* hds = xs  + 64*65;
    float* Wi  = hds + 64*65;        // 12288 paired
    float* Wh  = Wi  + 12288;        // 12288 paired
    float* hw  = Wh  + 12288;        // 64*16
    float* sc  = hw  + 64*16;        // 64*16
    const u64t* Wi64 = (const u64t*)Wi;
    const u64t* Wh64 = (const u64t*)Wh;
    const int tid = threadIdx.x;
    const int rbase = blockIdx.x * 64;

    for (int idx=tid; idx<4096; idx+=512){
        int r=idx>>6, d=idx&63;
        qs [r*65+d]=g_q[(rbase+r)*64+d];
        ks_[r*65+d]=g_k[(rbase+r)*64+d];
        vs [r*65+d]=g_v[(rbase+r)*64+d];
        hds[r*65+d]=hidden[(rbase+r)*64+d];
    }
    for (int idx=tid; idx<192*64; idx+=512){
        int g=idx>>6, d=idx&63;
        int gate=g>>6, rem=g&63;
        int pair=(rem>>5)&1, h=(rem>>4)&1, txx=rem&15;
        int pos = (d*96 + (gate*2+pair)*16 + txx)*2 + h;
        Wi[pos]=Wih_c[idx];
        Wh[pos]=Whh_c[idx];
    }
    {
        const float bh0 = b_hard[0], bh1 = b_hard[1];
        for (int idx=tid; idx<64*Tt; idx+=512){
            int r=idx/Tt, t=idx-r*Tt;
            int row = rbase + r;
            float L0 = g_lf[row*(2*Tt)+2*t]   + g_lb[row*(2*Tt)+2*t]   + bh0;
            float L1 = g_lf[row*(2*Tt)+2*t+1] + g_lb[row*(2*Tt)+2*t+1] + bh1;
            int gi = (row*Tt + t)*2;
            float u0 = gum[gi], u1 = gum[gi+1];
            float gg0 = -logf(-logf(u0+EPSg)+EPSg);
            float gg1 = -logf(-logf(u1+EPSg)+EPSg);
            float dlt = ((L1+gg1)-(L0+gg0)) * 100.0f;   // /TAU
            hw[r*16+t] = 1.0f/(1.0f+__expf(-dlt));
        }
    }
    __syncthreads();

    {
        int rp = tid>>3, qq = tid&7;
        #pragma unroll
        for (int s2=0; s2<2; ++s2){
            int t = qq + 8*s2;
            if (t < Tt){
                int ii = rp & 15;
                int jl = (rp & 48) + t + (t>=ii ? 1 : 0);
                float dot=0.f;
                #pragma unroll 8
                for (int d=0; d<64; ++d) dot += qs[rp*65+d]*ks_[jl*65+d];
                sc[rp*16+t] = dot*0.125f;
            }
        }
    }
    __syncthreads();
    if (tid < 64){
        int r=tid;
        float m=-1e30f;
        #pragma unroll
        for (int t=0;t<Tt;t++) m = fmaxf(m, sc[r*16+t]);
        float e[Tt]; float ssum=0.f;
        #pragma unroll
        for (int t=0;t<Tt;t++){ e[t]=__expf(sc[r*16+t]-m); ssum+=e[t]; }
        float inv = 1.0f/ssum;
        #pragma unroll
        for (int t=0;t<Tt;t++) sc[r*16+t] = e[t]*inv*hw[r*16+t];
    }
    __syncthreads();
    for (int idx=tid; idx<4096; idx+=512){
        int r=idx>>6, d=idx&63;
        int ii = r & 15, rb2 = r & 48;
        float x=0.f;
        #pragma unroll
        for (int t=0;t<Tt;t++){
            int jl = rb2 + t + (t>=ii ? 1 : 0);
            x += vs[jl*65+d]*sc[r*16+t];
        }
        xs[r*65+d]=x;
    }
    __syncthreads();

    const int ty=tid>>4, tx=tid&15; const int r0=ty*2;
    int dcol[4];
    #pragma unroll
    for (int k=0;k<4;k++) dcol[k] = tx + ((k>>1)<<5) + ((k&1)<<4);

    u64t arz0[2][2], arz1[2][2], ain[2][2], ahn[2][2];
    #pragma unroll
    for (int i=0;i<2;i++)
        #pragma unroll
        for (int p=0;p<2;p++){ arz0[i][p]=0ull; arz1[i][p]=0ull; ain[i][p]=0ull; ahn[i][p]=0ull; }

    #pragma unroll 2
    for (int dd=0; dd<64; ++dd){
        u64t pax[2], pah[2];
        #pragma unroll
        for (int i=0;i<2;i++){
            float ax=xs[(r0+i)*65+dd], ah=hds[(r0+i)*65+dd];
            pax[i]=pk(ax,ax); pah[i]=pk(ah,ah);
        }
        const u64t* wi = Wi64 + dd*96 + tx;
        const u64t* wh = Wh64 + dd*96 + tx;
        #pragma unroll
        for (int p=0;p<2;p++){
            u64t wir=wi[p*16], wiz=wi[(2+p)*16], win=wi[(4+p)*16];
            u64t whr=wh[p*16], whz=wh[(2+p)*16], whn=wh[(4+p)*16];
            #pragma unroll
            for (int i=0;i<2;i++){
                fma2(arz0[i][p], pax[i], wir); fma2(arz0[i][p], pah[i], whr);
                fma2(arz1[i][p], pax[i], wiz); fma2(arz1[i][p], pah[i], whz);
                fma2(ain [i][p], pax[i], win);
                fma2(ahn [i][p], pah[i], whn);
            }
        }
    }
    #pragma unroll
    for (int i=0;i<2;i++){
        int rl=r0+i;
        #pragma unroll
        for (int p=0;p<2;p++){
            float2 vrz0=up(arz0[i][p]), vrz1=up(arz1[i][p]), vin=up(ain[i][p]), vhn=up(ahn[i][p]);
            #pragma unroll
            for (int h=0;h<2;h++){
                int d = dcol[2*p+h];
                float a0 = h? vrz0.y : vrz0.x;
                float a1 = h? vrz1.y : vrz1.x;
                float a2 = h? vin.y  : vin.x;
                float a3 = h? vhn.y  : vhn.x;
                float r = sigm(a0 + bih_c[d]     + bhh_c[d]);
                float z = sigm(a1 + bih_c[d+64]  + bhh_c[d+64]);
                float n = tanh_(a2 + bih_c[d+128] + r*(a3 + bhh_c[d+128]));
                float ho = hds[rl*65+d];
                out[(rbase+rl)*64 + d] = (1.0f-z)*n + z*ho;
            }
        }
    }
}

// =====================================================================
extern "C" void kernel_launch(void* const* d_in, const int* in_sizes, int n_in,
                              void* d_out, int out_size)
{
    (void)in_sizes; (void)n_in; (void)out_size;
    const float* obs    = (const float*)d_in[0];
    const float* hidden = (const float*)d_in[1];
    const float* gum    = (const float*)d_in[2];
    const float* W_enc  = (const float*)d_in[3];
    const float* b_enc  = (const float*)d_in[4];
    const float* Wih_f  = (const float*)d_in[5];
    const float* Whh_f  = (const float*)d_in[6];
    const float* bih_f  = (const float*)d_in[7];
    const float* bhh_f  = (const float*)d_in[8];
    const float* Wih_b  = (const float*)d_in[9];
    const float* Whh_b  = (const float*)d_in[10];
    const float* bih_b  = (const float*)d_in[11];
    const float* bhh_b  = (const float*)d_in[12];
    const float* W_hard = (const float*)d_in[13];
    const float* b_hard = (const float*)d_in[14];
    const float* Wq     = (const float*)d_in[15];
    const float* Wk     = (const float*)d_in[16];
    const float* Wv     = (const float*)d_in[17];
    const float* b_v    = (const float*)d_in[18];
    const float* Wih_c  = (const float*)d_in[19];
    const float* Whh_c  = (const float*)d_in[20];
    const float* bih_c  = (const float*)d_in[21];
    const float* bhh_c  = (const float*)d_in[22];
    float* out = (float*)d_out;

    const int sm0 = (64*68 + 4096) * (int)sizeof(float);                    // 33,792 B
    const int sm1 = (64*68 + 4096) * (int)sizeof(float);                    // 33,792 B
    const int sm2 = (12288 + 64*66*2 + 2*12288) * (int)sizeof(float);       // 181,248 B  (FIXED)
    const int sm4 = (5*64*65 + 2*12288 + 2*64*16) * (int)sizeof(float);     // 189,696 B

    cudaFuncSetAttribute(k_enc,       cudaFuncAttributeMaxDynamicSharedMemorySize, sm0);
    cudaFuncSetAttribute(k_proj2,     cudaFuncAttributeMaxDynamicSharedMemorySize, sm1);
    cudaFuncSetAttribute(k_gru,       cudaFuncAttributeMaxDynamicSharedMemorySize, sm2);
    cudaFuncSetAttribute(k_attn_cell, cudaFuncAttributeMaxDynamicSharedMemorySize, sm4);

    k_enc<<<256, 256, sm0>>>(obs, W_enc, b_enc);
    k_proj2<<<dim3(256,5), 256, sm1>>>(Wq, Wk, Wv, b_v,
                                       Wih_f, bih_f, Wih_b, bih_b);
    k_gru<<<512, 256, sm2>>>(Whh_f, bhh_f, Whh_b, bhh_b, W_hard);
    k_attn_cell<<<256, 512, sm4>>>(hidden, gum, b_hard,
                                   Wih_c, Whh_c, bih_c, bhh_c, out);
}

// round 6
// speedup vs baseline: 1.3233x; 1.1874x over previous
#include <cuda_runtime.h>
#include <math.h>

#define NROWS 16384
#define Tt 15
#define EPSg 1e-10f

typedef unsigned long long u64t;

// ---------------- scratch ----------------
__device__ float g_h[NROWS*64];
__device__ float g_q[NROWS*64];
__device__ float g_k[NROWS*64];
__device__ float g_v[NROWS*64];
// paired layout: [row][ (gate*32+c)*2 + h ]  value = X[row][gate*64 + c + 32*h]
__device__ float g_Gf [NROWS*192];
__device__ float g_Cbf[NROWS*192];
__device__ float g_Gb [NROWS*192];
__device__ float g_Cbb[NROWS*192];
__device__ float g_lf[NROWS*2*Tt];
__device__ float g_lb[NROWS*2*Tt];

__device__ __forceinline__ float sigm(float x){ return 1.0f/(1.0f+__expf(-x)); }
__device__ __forceinline__ float tanh_(float x){ return 2.0f/(1.0f+__expf(-2.0f*x)) - 1.0f; }

__device__ __forceinline__ u64t pk(float x, float y){
    u64t r; asm("mov.b64 %0,{%1,%2};" : "=l"(r) : "f"(x), "f"(y)); return r;
}
__device__ __forceinline__ float2 up(u64t v){
    float2 r; asm("mov.b64 {%0,%1},%2;" : "=f"(r.x), "=f"(r.y) : "l"(v)); return r;
}
__device__ __forceinline__ void fma2(u64t& d, u64t a, u64t b){
    asm("fma.rn.f32x2 %0,%1,%2,%0;" : "+l"(d) : "l"(a), "l"(b));
}

// pairpos for proj micro-kernel weight tiles (16-lane pairing)
__device__ __forceinline__ int pairpos64(int d, int c){
    return ((d<<5) + (((c>>5)&1)<<4) + (c&15))*2 + ((c>>4)&1);
}

// =====================================================================
// K0: encoder. h_enc = relu(obs @ W_enc + b_enc) -> g_h
// =====================================================================
__global__ __launch_bounds__(256)
void k_enc(const float* __restrict__ obs,
           const float* __restrict__ W_enc, const float* __restrict__ b_enc)
{
    extern __shared__ float sm[];
    float* Os = sm;                 // 64*68
    float* Wt = sm + 64*68;         // 4096 paired
    const u64t* Wt64 = (const u64t*)Wt;
    const int tid = threadIdx.x;
    const int rbase = blockIdx.x * 64;
    const int ty = tid >> 4, tx = tid & 15;
    const int r0 = ty * 4;
    int dcol[4];
    #pragma unroll
    for (int k=0;k<4;k++) dcol[k] = tx + ((k>>1)<<5) + ((k&1)<<4);

    for (int idx = tid; idx < 4096; idx += 256) {
        int r = idx >> 6, c = idx & 63;
        Os[r*68+c] = obs[(rbase+r)*64 + c];
        Wt[pairpos64(r, c)] = W_enc[idx];
    }
    __syncthreads();

    u64t acc[4][2];
    #pragma unroll
    for (int i=0;i<4;i++){ acc[i][0]=0ull; acc[i][1]=0ull; }
    for (int dd=0; dd<64; ++dd){
        u64t pa[4];
        #pragma unroll
        for (int i=0;i<4;i++){ float a=Os[(r0+i)*68+dd]; pa[i]=pk(a,a); }
        #pragma unroll
        for (int p=0;p<2;p++){
            u64t w = Wt64[dd*32 + p*16 + tx];
            #pragma unroll
            for (int i=0;i<4;i++) fma2(acc[i][p], pa[i], w);
        }
    }
    #pragma unroll
    for (int i=0;i<4;i++)
        #pragma unroll
        for (int p=0;p<2;p++){
            float2 v = up(acc[i][p]);
            int d0 = dcol[2*p], d1 = dcol[2*p+1];
            g_h[(rbase+r0+i)*64 + d0] = fmaxf(v.x + b_enc[d0], 0.0f);
            g_h[(rbase+r0+i)*64 + d1] = fmaxf(v.y + b_enc[d1], 0.0f);
        }
}

// =====================================================================
// K1: projections. grid (256 tiles, 5 groups), 3 segments per block.
// =====================================================================
__global__ __launch_bounds__(256)
void k_proj2(const float* __restrict__ Wq, const float* __restrict__ Wk,
             const float* __restrict__ Wv, const float* __restrict__ b_v,
             const float* __restrict__ Wih_f, const float* __restrict__ bih_f,
             const float* __restrict__ Wih_b, const float* __restrict__ bih_b)
{
    extern __shared__ float sm[];
    float* Hs = sm;                 // 64*68
    float* Wt = sm + 64*68;         // 4096 paired
    const u64t* Wt64 = (const u64t*)Wt;
    const int tid = threadIdx.x;
    const int rbase = blockIdx.x * 64;
    const int gy = blockIdx.y;
    const int ty = tid >> 4, tx = tid & 15;
    const int r0 = ty * 4;
    int dcol[4];
    #pragma unroll
    for (int k=0;k<4;k++) dcol[k] = tx + ((k>>1)<<5) + ((k&1)<<4);

    for (int idx = tid; idx < 4096; idx += 256) {
        int r = idx >> 6, c = idx & 63;
        Hs[r*68+c] = g_h[(rbase+r)*64 + c];
    }

    for (int j = 0; j < 3; ++j){
        const float* Wsrc=nullptr; const float* bias=nullptr;
        float* dst=nullptr; int mode; int doRelu=0; int gate=j;
        if (gy==0){
            mode=0;
            if (j==0){ Wsrc=Wq; dst=g_q; }
            else if (j==1){ Wsrc=Wk; dst=g_k; }
            else { Wsrc=Wv; dst=g_v; bias=b_v; doRelu=1; }
        } else if (gy==1){ mode=1; Wsrc=Wih_f; dst=g_Cbf; bias=bih_f; }
        else if   (gy==2){ mode=2; Wsrc=Wih_f; dst=g_Gf; }
        else if   (gy==3){ mode=1; Wsrc=Wih_b; dst=g_Cbb; bias=bih_b; }
        else              { mode=2; Wsrc=Wih_b; dst=g_Gb; }
        const int colBase = gate*64;

        __syncthreads();
        for (int idx = tid; idx < 4096; idx += 256){
            int hi = idx >> 6, lo = idx & 63;
            if (mode==0) Wt[pairpos64(hi, lo)] = Wsrc[idx];
            else {
                int off = (colBase+hi)*128 + lo + (mode==2 ? 64 : 0);
                Wt[pairpos64(lo, hi)] = Wsrc[off];
            }
        }
        __syncthreads();

        u64t acc[4][2];
        #pragma unroll
        for (int i=0;i<4;i++){ acc[i][0]=0ull; acc[i][1]=0ull; }
        for (int dd=0; dd<64; ++dd){
            u64t pa[4];
            #pragma unroll
            for (int i=0;i<4;i++){ float a=Hs[(r0+i)*68+dd]; pa[i]=pk(a,a); }
            #pragma unroll
            for (int p=0;p<2;p++){
                u64t w = Wt64[dd*32 + p*16 + tx];
                #pragma unroll
                for (int i=0;i<4;i++) fma2(acc[i][p], pa[i], w);
            }
        }

        if (mode==0){
            #pragma unroll
            for (int i=0;i<4;i++)
                #pragma unroll
                for (int p=0;p<2;p++){
                    float2 v = up(acc[i][p]);
                    #pragma unroll
                    for (int h=0;h<2;h++){
                        int d = dcol[2*p+h];
                        float vv = (h ? v.y : v.x) + (bias ? bias[d] : 0.0f);
                        if (doRelu) vv = fmaxf(vv, 0.0f);
                        dst[(rbase+r0+i)*64 + d] = vv;
                    }
                }
        } else {
            float b0=0.f,b1=0.f,b2=0.f,b3=0.f;
            if (bias){
                b0=bias[colBase+tx]; b1=bias[colBase+tx+16];
                b2=bias[colBase+tx+32]; b3=bias[colBase+tx+48];
            }
            u64t* dst64 = (u64t*)dst;
            #pragma unroll
            for (int i=0;i<4;i++){
                float2 v0 = up(acc[i][0]);   // cols tx, tx+16
                float2 v1 = up(acc[i][1]);   // cols tx+32, tx+48
                int row = rbase + r0 + i;
                dst64[row*96 + gate*32 + tx]      = pk(v0.x + b0, v1.x + b2);
                dst64[row*96 + gate*32 + tx + 16] = pk(v0.y + b1, v1.y + b3);
            }
        }
    }
}

// =====================================================================
// K2: both GRU directions. 512 blocks x 256 threads, occ 2.
// Scalar FFMA mainloop. Warp owns 8 rows; lane owns cols (lane, lane+32).
// G/Cb read directly from gmem (paired float2 rows) in the epilogue.
// smem: Wp 48K + hs 17K = 66,560 B per block -> 2 blocks/SM.
// =====================================================================
__global__ __launch_bounds__(256,2)
void k_gru(const float* __restrict__ Whh_f, const float* __restrict__ bhh_f,
           const float* __restrict__ Whh_b, const float* __restrict__ bhh_b,
           const float* __restrict__ W_hard)
{
    extern __shared__ float sm[];
    float*  Wp  = sm;                 // 12288 floats (paired)
    float*  hs  = sm + 12288;         // 64*68 floats
    const float2* Wp2 = (const float2*)Wp;
    const int tid  = threadIdx.x;
    const int wid  = tid >> 5;
    const int lane = tid & 31;
    const int fwd = (blockIdx.x < 256);
    const int rbase = (blockIdx.x & 255) * 64;
    const int r0 = wid * 8;
    const float2* G2  = (const float2*)(fwd ? g_Gf  : g_Gb);
    const float2* Cb2 = (const float2*)(fwd ? g_Cbf : g_Cbb);
    const float* Whh   = fwd ? Whh_f : Whh_b;
    const float* bhh   = fwd ? bhh_f : bhh_b;
    float* lout = fwd ? g_lf : g_lb;

    // weights: Wp2[(dd*3+g)*32 + c] = ( Whh[(g*64+c)*64+dd], Whh[(g*64+c+32)*64+dd] )
    for (int i = tid; i < 12288; i += 256){
        int gd = i >> 6, dd = i & 63;
        int g = gd >> 6, cc = gd & 63;
        int c = cc & 31, h = cc >> 5;
        Wp[(((dd*3 + g)*32 + c) << 1) + h] = Whh[i];
    }
    for (int i = tid; i < 64*68; i += 256) hs[i] = 0.0f;

    // per-lane constants
    float br_lo=bhh[lane],     br_hi=bhh[lane+32];
    float bz_lo=bhh[64+lane],  bz_hi=bhh[96+lane];
    float bn_lo=bhh[128+lane], bn_hi=bhh[160+lane];
    int wb = fwd ? 0 : 64;
    float w0_lo=W_hard[(wb+lane)*2],    w0_hi=W_hard[(wb+lane+32)*2];
    float w1_lo=W_hard[(wb+lane)*2+1],  w1_hi=W_hard[(wb+lane+32)*2+1];
    __syncthreads();

    for (int step=0; step<Tt; ++step){
        const int t = fwd ? step : (Tt-1-step);
        float2 aR[8], aZ[8], aN[8];
        #pragma unroll
        for (int i=0;i<8;i++){
            aR[i]=make_float2(0.f,0.f); aZ[i]=make_float2(0.f,0.f); aN[i]=make_float2(0.f,0.f);
        }

        if (step){
            #pragma unroll 2
            for (int dd=0; dd<64; dd+=2){
                float2 w00 = Wp2[(dd*3+0)*32 + lane];
                float2 w01 = Wp2[(dd*3+1)*32 + lane];
                float2 w02 = Wp2[(dd*3+2)*32 + lane];
                float2 w10 = Wp2[((dd+1)*3+0)*32 + lane];
                float2 w11 = Wp2[((dd+1)*3+1)*32 + lane];
                float2 w12 = Wp2[((dd+1)*3+2)*32 + lane];
                #pragma unroll
                for (int i=0;i<8;i++){
                    float2 a = *(const float2*)&hs[(r0+i)*68 + dd];  // broadcast
                    aR[i].x += a.x*w00.x; aR[i].y += a.x*w00.y;
                    aZ[i].x += a.x*w01.x; aZ[i].y += a.x*w01.y;
                    aN[i].x += a.x*w02.x; aN[i].y += a.x*w02.y;
                    aR[i].x += a.y*w10.x; aR[i].y += a.y*w10.y;
                    aZ[i].x += a.y*w11.x; aZ[i].y += a.y*w11.y;
                    aN[i].x += a.y*w12.x; aN[i].y += a.y*w12.y;
                }
            }
        }

        float l0[8], l1[8];
        #pragma unroll
        for (int i=0;i<8;i++){
            int rl = r0+i;
            int ii = rl & 15;
            int jl = (rl & 48) + t + (t>=ii ? 1 : 0);
            size_t rg = (size_t)(rbase + rl)*96;
            size_t jg = (size_t)(rbase + jl)*96;
            float2 c0 = Cb2[rg      + lane];
            float2 c1 = Cb2[rg + 32 + lane];
            float2 c2 = Cb2[rg + 64 + lane];
            float2 g0 = G2 [jg      + lane];
            float2 g1 = G2 [jg + 32 + lane];
            float2 g2 = G2 [jg + 64 + lane];
            float ho_lo = hs[rl*68 + lane];
            float ho_hi = hs[rl*68 + 32 + lane];
            float r_lo = sigm(c0.x + g0.x + aR[i].x + br_lo);
            float r_hi = sigm(c0.y + g0.y + aR[i].y + br_hi);
            float z_lo = sigm(c1.x + g1.x + aZ[i].x + bz_lo);
            float z_hi = sigm(c1.y + g1.y + aZ[i].y + bz_hi);
            float n_lo = tanh_(c2.x + g2.x + r_lo*(aN[i].x + bn_lo));
            float n_hi = tanh_(c2.y + g2.y + r_hi*(aN[i].y + bn_hi));
            float hv_lo = (1.0f - z_lo)*n_lo + z_lo*ho_lo;
            float hv_hi = (1.0f - z_hi)*n_hi + z_hi*ho_hi;
            hs[rl*68 + lane]      = hv_lo;
            hs[rl*68 + 32 + lane] = hv_hi;
            l0[i] = hv_lo*w0_lo + hv_hi*w0_hi;
            l1[i] = hv_lo*w1_lo + hv_hi*w1_hi;
        }
        #pragma unroll
        for (int off=16; off>=1; off>>=1){
            #pragma unroll
            for (int i=0;i<8;i++){
                l0[i] += __shfl_xor_sync(0xffffffffu, l0[i], off);
                l1[i] += __shfl_xor_sync(0xffffffffu, l1[i], off);
            }
        }
        #pragma unroll
        for (int i=0;i<8;i++){
            if (lane == i){
                ((u64t*)lout)[(size_t)(rbase + r0 + i)*Tt + t] = pk(l0[i], l1[i]);
            }
        }
    }
}

// =====================================================================
// K3: gumbel hard weights + attention + final GRU cell. 512 threads.
// =====================================================================
__global__ __launch_bounds__(512,1)
void k_attn_cell(const float* __restrict__ hidden,
                 const float* __restrict__ gum,
                 const float* __restrict__ b_hard,
                 const float* __restrict__ Wih_c, const float* __restrict__ Whh_c,
                 const float* __restrict__ bih_c, const float* __restrict__ bhh_c,
                 float* __restrict__ out)
{
    extern __shared__ float sm[];
    float* qs  = sm;                 // 64*65
    float* ks_ = qs  + 64*65;
    float* vs  = ks_ + 64*65;
    float* xs  = vs  + 64*65;
    float* hds = xs  + 64*65;
    float* Wi  = hds + 64*65;        // 12288 paired
    float* Wh  = Wi  + 12288;        // 12288 paired
    float* hw  = Wh  + 12288;        // 64*16
    float* sc  = hw  + 64*16;        // 64*16
    const u64t* Wi64 = (const u64t*)Wi;
    const u64t* Wh64 = (const u64t*)Wh;
    const int tid = threadIdx.x;
    const int rbase = blockIdx.x * 64;

    for (int idx=tid; idx<4096; idx+=512){
        int r=idx>>6, d=idx&63;
        qs [r*65+d]=g_q[(rbase+r)*64+d];
        ks_[r*65+d]=g_k[(rbase+r)*64+d];
        vs [r*65+d]=g_v[(rbase+r)*64+d];
        hds[r*65+d]=hidden[(rbase+r)*64+d];
    }
    for (int idx=tid; idx<192*64; idx+=512){
        int g=idx>>6, d=idx&63;
        int gate=g>>6, rem=g&63;
        int pair=(rem>>5)&1, h=(rem>>4)&1, txx=rem&15;
        int pos = (d*96 + (gate*2+pair)*16 + txx)*2 + h;
        Wi[pos]=Wih_c[idx];
        Wh[pos]=Whh_c[idx];
    }
    {
        const float bh0 = b_hard[0], bh1 = b_hard[1];
        for (int idx=tid; idx<64*Tt; idx+=512){
            int r=idx/Tt, t=idx-r*Tt;
            int row = rbase + r;
            float L0 = g_lf[row*(2*Tt)+2*t]   + g_lb[row*(2*Tt)+2*t]   + bh0;
            float L1 = g_lf[row*(2*Tt)+2*t+1] + g_lb[row*(2*Tt)+2*t+1] + bh1;
            int gi = (row*Tt + t)*2;
            float u0 = gum[gi], u1 = gum[gi+1];
            float gg0 = -logf(-logf(u0+EPSg)+EPSg);
            float gg1 = -logf(-logf(u1+EPSg)+EPSg);
            float dlt = ((L1+gg1)-(L0+gg0)) * 100.0f;   // /TAU
            hw[r*16+t] = 1.0f/(1.0f+__expf(-dlt));
        }
    }
    __syncthreads();

    {
        int rp = tid>>3, qq = tid&7;
        #pragma unroll
        for (int s2=0; s2<2; ++s2){
            int t = qq + 8*s2;
            if (t < Tt){
                int ii = rp & 15;
                int jl = (rp & 48) + t + (t>=ii ? 1 : 0);
                float dot=0.f;
                #pragma unroll 8
                for (int d=0; d<64; ++d) dot += qs[rp*65+d]*ks_[jl*65+d];
                sc[rp*16+t] = dot*0.125f;
            }
        }
    }
    __syncthreads();
    if (tid < 64){
        int r=tid;
        float m=-1e30f;
        #pragma unroll
        for (int t=0;t<Tt;t++) m = fmaxf(m, sc[r*16+t]);
        float e[Tt]; float ssum=0.f;
        #pragma unroll
        for (int t=0;t<Tt;t++){ e[t]=__expf(sc[r*16+t]-m); ssum+=e[t]; }
        float inv = 1.0f/ssum;
        #pragma unroll
        for (int t=0;t<Tt;t++) sc[r*16+t] = e[t]*inv*hw[r*16+t];
    }
    __syncthreads();
    for (int idx=tid; idx<4096; idx+=512){
        int r=idx>>6, d=idx&63;
        int ii = r & 15, rb2 = r & 48;
        float x=0.f;
        #pragma unroll
        for (int t=0;t<Tt;t++){
            int jl = rb2 + t + (t>=ii ? 1 : 0);
            x += vs[jl*65+d]*sc[r*16+t];
        }
        xs[r*65+d]=x;
    }
    __syncthreads();

    const int ty=tid>>4, tx=tid&15; const int r0=ty*2;
    int dcol[4];
    #pragma unroll
    for (int k=0;k<4;k++) dcol[k] = tx + ((k>>1)<<5) + ((k&1)<<4);

    u64t arz0[2][2], arz1[2][2], ain[2][2], ahn[2][2];
    #pragma unroll
    for (int i=0;i<2;i++)
        #pragma unroll
        for (int p=0;p<2;p++){ arz0[i][p]=0ull; arz1[i][p]=0ull; ain[i][p]=0ull; ahn[i][p]=0ull; }

    #pragma unroll 2
    for (int dd=0; dd<64; ++dd){
        u64t pax[2], pah[2];
        #pragma unroll
        for (int i=0;i<2;i++){
            float ax=xs[(r0+i)*65+dd], ah=hds[(r0+i)*65+dd];
            pax[i]=pk(ax,ax); pah[i]=pk(ah,ah);
        }
        const u64t* wi = Wi64 + dd*96 + tx;
        const u64t* wh = Wh64 + dd*96 + tx;
        #pragma unroll
        for (int p=0;p<2;p++){
            u64t wir=wi[p*16], wiz=wi[(2+p)*16], win=wi[(4+p)*16];
            u64t whr=wh[p*16], whz=wh[(2+p)*16], whn=wh[(4+p)*16];
            #pragma unroll
            for (int i=0;i<2;i++){
                fma2(arz0[i][p], pax[i], wir); fma2(arz0[i][p], pah[i], whr);
                fma2(arz1[i][p], pax[i], wiz); fma2(arz1[i][p], pah[i], whz);
                fma2(ain [i][p], pax[i], win);
                fma2(ahn [i][p], pah[i], whn);
            }
        }
    }
    #pragma unroll
    for (int i=0;i<2;i++){
        int rl=r0+i;
        #pragma unroll
        for (int p=0;p<2;p++){
            float2 vrz0=up(arz0[i][p]), vrz1=up(arz1[i][p]), vin=up(ain[i][p]), vhn=up(ahn[i][p]);
            #pragma unroll
            for (int h=0;h<2;h++){
                int d = dcol[2*p+h];
                float a0 = h? vrz0.y : vrz0.x;
                float a1 = h? vrz1.y : vrz1.x;
                float a2 = h? vin.y  : vin.x;
                float a3 = h? vhn.y  : vhn.x;
                float r = sigm(a0 + bih_c[d]     + bhh_c[d]);
                float z = sigm(a1 + bih_c[d+64]  + bhh_c[d+64]);
                float n = tanh_(a2 + bih_c[d+128] + r*(a3 + bhh_c[d+128]));
                float ho = hds[rl*65+d];
                out[(rbase+rl)*64 + d] = (1.0f-z)*n + z*ho;
            }
        }
    }
}

// =====================================================================
extern "C" void kernel_launch(void* const* d_in, const int* in_sizes, int n_in,
                              void* d_out, int out_size)
{
    (void)in_sizes; (void)n_in; (void)out_size;
    const float* obs    = (const float*)d_in[0];
    const float* hidden = (const float*)d_in[1];
    const float* gum    = (const float*)d_in[2];
    const float* W_enc  = (const float*)d_in[3];
    const float* b_enc  = (const float*)d_in[4];
    const float* Wih_f  = (const float*)d_in[5];
    const float* Whh_f  = (const float*)d_in[6];
    const float* bih_f  = (const float*)d_in[7];
    const float* bhh_f  = (const float*)d_in[8];
    const float* Wih_b  = (const float*)d_in[9];
    const float* Whh_b  = (const float*)d_in[10];
    const float* bih_b  = (const float*)d_in[11];
    const float* bhh_b  = (const float*)d_in[12];
    const float* W_hard = (const float*)d_in[13];
    const float* b_hard = (const float*)d_in[14];
    const float* Wq     = (const float*)d_in[15];
    const float* Wk     = (const float*)d_in[16];
    const float* Wv     = (const float*)d_in[17];
    const float* b_v    = (const float*)d_in[18];
    const float* Wih_c  = (const float*)d_in[19];
    const float* Whh_c  = (const float*)d_in[20];
    const float* bih_c  = (const float*)d_in[21];
    const float* bhh_c  = (const float*)d_in[22];
    float* out = (float*)d_out;

    const int sm0 = (64*68 + 4096) * (int)sizeof(float);                    // 33,792 B
    const int sm1 = (64*68 + 4096) * (int)sizeof(float);                    // 33,792 B
    const int sm2 = (12288 + 64*68) * (int)sizeof(float);                   // 66,560 B
    const int sm4 = (5*64*65 + 2*12288 + 2*64*16) * (int)sizeof(float);     // 189,696 B

    cudaFuncSetAttribute(k_enc,       cudaFuncAttributeMaxDynamicSharedMemorySize, sm0);
    cudaFuncSetAttribute(k_proj2,     cudaFuncAttributeMaxDynamicSharedMemorySize, sm1);
    cudaFuncSetAttribute(k_gru,       cudaFuncAttributeMaxDynamicSharedMemorySize, sm2);
    cudaFuncSetAttribute(k_attn_cell, cudaFuncAttributeMaxDynamicSharedMemorySize, sm4);

    k_enc<<<256, 256, sm0>>>(obs, W_enc, b_enc);
    k_proj2<<<dim3(256,5), 256, sm1>>>(Wq, Wk, Wv, b_v,
                                       Wih_f, bih_f, Wih_b, bih_b);
    k_gru<<<512, 256, sm2>>>(Whh_f, bhh_f, Whh_b, bhh_b, W_hard);
    k_attn_cell<<<256, 512, sm4>>>(hidden, gum, b_hard,
                                   Wih_c, Whh_c, bih_c, bhh_c, out);
}

// round 8
// speedup vs baseline: 1.4061x; 1.0626x over previous
#include <cuda_runtime.h>
#include <math.h>

#define NROWS 16384
#define Tt 15
#define EPSg 1e-10f

typedef unsigned long long u64t;

// ---------------- scratch ----------------
__device__ float g_h[NROWS*64];
__device__ float g_q[NROWS*64];
__device__ float g_k[NROWS*64];
__device__ float g_v[NROWS*64];
// paired layout: [row][ (gate*32+c)*2 + h ]  value = X[row][gate*64 + c + 32*h]
__device__ float g_Gf [NROWS*192];
__device__ float g_Cbf[NROWS*192];
__device__ float g_Gb [NROWS*192];
__device__ float g_Cbb[NROWS*192];
__device__ float g_lf[NROWS*2*Tt];
__device__ float g_lb[NROWS*2*Tt];
// packed cell weights: float4 at ((dd*3+gate)*32+c):
//   ( Wih[(gate*64+c)*64+dd], Wih[(gate*64+c+32)*64+dd],
//     Whh[(gate*64+c)*64+dd], Whh[(gate*64+c+32)*64+dd] )
__device__ float g_Wc[64*3*32*4];

__device__ __forceinline__ float sigm(float x){ return 1.0f/(1.0f+__expf(-x)); }
__device__ __forceinline__ float tanh_(float x){ return 2.0f/(1.0f+__expf(-2.0f*x)) - 1.0f; }

__device__ __forceinline__ u64t pk(float x, float y){
    u64t r; asm("mov.b64 %0,{%1,%2};" : "=l"(r) : "f"(x), "f"(y)); return r;
}
__device__ __forceinline__ float2 up(u64t v){
    float2 r; asm("mov.b64 {%0,%1},%2;" : "=f"(r.x), "=f"(r.y) : "l"(v)); return r;
}
__device__ __forceinline__ void fma2(u64t& d, u64t a, u64t b){
    asm("fma.rn.f32x2 %0,%1,%2,%0;" : "+l"(d) : "l"(a), "l"(b));
}

// pairpos for proj micro-kernel weight tiles (16-lane pairing)
__device__ __forceinline__ int pairpos64(int d, int c){
    return ((d<<5) + (((c>>5)&1)<<4) + (c&15))*2 + ((c>>4)&1);
}

// =====================================================================
// K0: encoder. h_enc = relu(obs @ W_enc + b_enc) -> g_h
// =====================================================================
__global__ __launch_bounds__(256)
void k_enc(const float* __restrict__ obs,
           const float* __restrict__ W_enc, const float* __restrict__ b_enc)
{
    extern __shared__ float sm[];
    float* Os = sm;                 // 64*68
    float* Wt = sm + 64*68;         // 4096 paired
    const u64t* Wt64 = (const u64t*)Wt;
    const int tid = threadIdx.x;
    const int rbase = blockIdx.x * 64;
    const int ty = tid >> 4, tx = tid & 15;
    const int r0 = ty * 4;
    int dcol[4];
    #pragma unroll
    for (int k=0;k<4;k++) dcol[k] = tx + ((k>>1)<<5) + ((k&1)<<4);

    for (int idx = tid; idx < 4096; idx += 256) {
        int r = idx >> 6, c = idx & 63;
        Os[r*68+c] = obs[(rbase+r)*64 + c];
        Wt[pairpos64(r, c)] = W_enc[idx];
    }
    __syncthreads();

    u64t acc[4][2];
    #pragma unroll
    for (int i=0;i<4;i++){ acc[i][0]=0ull; acc[i][1]=0ull; }
    for (int dd=0; dd<64; ++dd){
        u64t pa[4];
        #pragma unroll
        for (int i=0;i<4;i++){ float a=Os[(r0+i)*68+dd]; pa[i]=pk(a,a); }
        #pragma unroll
        for (int p=0;p<2;p++){
            u64t w = Wt64[dd*32 + p*16 + tx];
            #pragma unroll
            for (int i=0;i<4;i++) fma2(acc[i][p], pa[i], w);
        }
    }
    #pragma unroll
    for (int i=0;i<4;i++)
        #pragma unroll
        for (int p=0;p<2;p++){
            float2 v = up(acc[i][p]);
            int d0 = dcol[2*p], d1 = dcol[2*p+1];
            g_h[(rbase+r0+i)*64 + d0] = fmaxf(v.x + b_enc[d0], 0.0f);
            g_h[(rbase+r0+i)*64 + d1] = fmaxf(v.y + b_enc[d1], 0.0f);
        }
}

// =====================================================================
// K0b: pack cell weights into g_Wc (float4 per (dd,gate,lane))
// =====================================================================
__global__ __launch_bounds__(256)
void k_packW(const float* __restrict__ Wih_c, const float* __restrict__ Whh_c)
{
    int idx = blockIdx.x * 256 + threadIdx.x;   // 6144 float4 slots
    if (idx >= 6144) return;
    int dd = idx / 96;
    int rem = idx - dd*96;
    int gate = rem >> 5;
    int c = rem & 31;
    float4 w;
    w.x = Wih_c[(gate*64 + c     )*64 + dd];
    w.y = Wih_c[(gate*64 + c + 32)*64 + dd];
    w.z = Whh_c[(gate*64 + c     )*64 + dd];
    w.w = Whh_c[(gate*64 + c + 32)*64 + dd];
    ((float4*)g_Wc)[idx] = w;
}

// =====================================================================
// K1: projections. grid (256 tiles, 5 groups), 3 segments per block.
// =====================================================================
__global__ __launch_bounds__(256)
void k_proj2(const float* __restrict__ Wq, const float* __restrict__ Wk,
             const float* __restrict__ Wv, const float* __restrict__ b_v,
             const float* __restrict__ Wih_f, const float* __restrict__ bih_f,
             const float* __restrict__ Wih_b, const float* __restrict__ bih_b)
{
    extern __shared__ float sm[];
    float* Hs = sm;                 // 64*68
    float* Wt = sm + 64*68;         // 4096 paired
    const u64t* Wt64 = (const u64t*)Wt;
    const int tid = threadIdx.x;
    const int rbase = blockIdx.x * 64;
    const int gy = blockIdx.y;
    const int ty = tid >> 4, tx = tid & 15;
    const int r0 = ty * 4;
    int dcol[4];
    #pragma unroll
    for (int k=0;k<4;k++) dcol[k] = tx + ((k>>1)<<5) + ((k&1)<<4);

    for (int idx = tid; idx < 4096; idx += 256) {
        int r = idx >> 6, c = idx & 63;
        Hs[r*68+c] = g_h[(rbase+r)*64 + c];
    }

    for (int j = 0; j < 3; ++j){
        const float* Wsrc=nullptr; const float* bias=nullptr;
        float* dst=nullptr; int mode; int doRelu=0; int gate=j;
        if (gy==0){
            mode=0;
            if (j==0){ Wsrc=Wq; dst=g_q; }
            else if (j==1){ Wsrc=Wk; dst=g_k; }
            else { Wsrc=Wv; dst=g_v; bias=b_v; doRelu=1; }
        } else if (gy==1){ mode=1; Wsrc=Wih_f; dst=g_Cbf; bias=bih_f; }
        else if   (gy==2){ mode=2; Wsrc=Wih_f; dst=g_Gf; }
        else if   (gy==3){ mode=1; Wsrc=Wih_b; dst=g_Cbb; bias=bih_b; }
        else              { mode=2; Wsrc=Wih_b; dst=g_Gb; }
        const int colBase = gate*64;

        __syncthreads();
        for (int idx = tid; idx < 4096; idx += 256){
            int hi = idx >> 6, lo = idx & 63;
            if (mode==0) Wt[pairpos64(hi, lo)] = Wsrc[idx];
            else {
                int off = (colBase+hi)*128 + lo + (mode==2 ? 64 : 0);
                Wt[pairpos64(lo, hi)] = Wsrc[off];
            }
        }
        __syncthreads();

        u64t acc[4][2];
        #pragma unroll
        for (int i=0;i<4;i++){ acc[i][0]=0ull; acc[i][1]=0ull; }
        for (int dd=0; dd<64; ++dd){
            u64t pa[4];
            #pragma unroll
            for (int i=0;i<4;i++){ float a=Hs[(r0+i)*68+dd]; pa[i]=pk(a,a); }
            #pragma unroll
            for (int p=0;p<2;p++){
                u64t w = Wt64[dd*32 + p*16 + tx];
                #pragma unroll
                for (int i=0;i<4;i++) fma2(acc[i][p], pa[i], w);
            }
        }

        if (mode==0){
            #pragma unroll
            for (int i=0;i<4;i++)
                #pragma unroll
                for (int p=0;p<2;p++){
                    float2 v = up(acc[i][p]);
                    #pragma unroll
                    for (int h=0;h<2;h++){
                        int d = dcol[2*p+h];
                        float vv = (h ? v.y : v.x) + (bias ? bias[d] : 0.0f);
                        if (doRelu) vv = fmaxf(vv, 0.0f);
                        dst[(rbase+r0+i)*64 + d] = vv;
                    }
                }
        } else {
            float b0=0.f,b1=0.f,b2=0.f,b3=0.f;
            if (bias){
                b0=bias[colBase+tx]; b1=bias[colBase+tx+16];
                b2=bias[colBase+tx+32]; b3=bias[colBase+tx+48];
            }
            u64t* dst64 = (u64t*)dst;
            #pragma unroll
            for (int i=0;i<4;i++){
                float2 v0 = up(acc[i][0]);   // cols tx, tx+16
                float2 v1 = up(acc[i][1]);   // cols tx+32, tx+48
                int row = rbase + r0 + i;
                dst64[row*96 + gate*32 + tx]      = pk(v0.x + b0, v1.x + b2);
                dst64[row*96 + gate*32 + tx + 16] = pk(v0.y + b1, v1.y + b3);
            }
        }
    }
}

// =====================================================================
// K2: both GRU directions. 512 blocks x 256 threads, occ 2.
// Scalar FFMA mainloop. Warp owns 8 rows; lane owns cols (lane, lane+32).
// =====================================================================
__global__ __launch_bounds__(256,2)
void k_gru(const float* __restrict__ Whh_f, const float* __restrict__ bhh_f,
           const float* __restrict__ Whh_b, const float* __restrict__ bhh_b,
           const float* __restrict__ W_hard)
{
    extern __shared__ float sm[];
    float*  Wp  = sm;                 // 12288 floats (paired)
    float*  hs  = sm + 12288;         // 64*68 floats
    const float2* Wp2 = (const float2*)Wp;
    const int tid  = threadIdx.x;
    const int wid  = tid >> 5;
    const int lane = tid & 31;
    const int fwd = (blockIdx.x < 256);
    const int rbase = (blockIdx.x & 255) * 64;
    const int r0 = wid * 8;
    const float2* G2  = (const float2*)(fwd ? g_Gf  : g_Gb);
    const float2* Cb2 = (const float2*)(fwd ? g_Cbf : g_Cbb);
    const float* Whh   = fwd ? Whh_f : Whh_b;
    const float* bhh   = fwd ? bhh_f : bhh_b;
    float* lout = fwd ? g_lf : g_lb;

    for (int i = tid; i < 12288; i += 256){
        int gd = i >> 6, dd = i & 63;
        int g = gd >> 6, cc = gd & 63;
        int c = cc & 31, h = cc >> 5;
        Wp[(((dd*3 + g)*32 + c) << 1) + h] = Whh[i];
    }
    for (int i = tid; i < 64*68; i += 256) hs[i] = 0.0f;

    float br_lo=bhh[lane],     br_hi=bhh[lane+32];
    float bz_lo=bhh[64+lane],  bz_hi=bhh[96+lane];
    float bn_lo=bhh[128+lane], bn_hi=bhh[160+lane];
    int wb = fwd ? 0 : 64;
    float w0_lo=W_hard[(wb+lane)*2],    w0_hi=W_hard[(wb+lane+32)*2];
    float w1_lo=W_hard[(wb+lane)*2+1],  w1_hi=W_hard[(wb+lane+32)*2+1];
    __syncthreads();

    for (int step=0; step<Tt; ++step){
        const int t = fwd ? step : (Tt-1-step);
        float2 aR[8], aZ[8], aN[8];
        #pragma unroll
        for (int i=0;i<8;i++){
            aR[i]=make_float2(0.f,0.f); aZ[i]=make_float2(0.f,0.f); aN[i]=make_float2(0.f,0.f);
        }

        if (step){
            #pragma unroll 2
            for (int dd=0; dd<64; dd+=2){
                float2 w00 = Wp2[(dd*3+0)*32 + lane];
                float2 w01 = Wp2[(dd*3+1)*32 + lane];
                float2 w02 = Wp2[(dd*3+2)*32 + lane];
                float2 w10 = Wp2[((dd+1)*3+0)*32 + lane];
                float2 w11 = Wp2[((dd+1)*3+1)*32 + lane];
                float2 w12 = Wp2[((dd+1)*3+2)*32 + lane];
                #pragma unroll
                for (int i=0;i<8;i++){
                    float2 a = *(const float2*)&hs[(r0+i)*68 + dd];  // broadcast
                    aR[i].x += a.x*w00.x; aR[i].y += a.x*w00.y;
                    aZ[i].x += a.x*w01.x; aZ[i].y += a.x*w01.y;
                    aN[i].x += a.x*w02.x; aN[i].y += a.x*w02.y;
                    aR[i].x += a.y*w10.x; aR[i].y += a.y*w10.y;
                    aZ[i].x += a.y*w11.x; aZ[i].y += a.y*w11.y;
                    aN[i].x += a.y*w12.x; aN[i].y += a.y*w12.y;
                }
            }
        }

        float l0[8], l1[8];
        #pragma unroll
        for (int i=0;i<8;i++){
            int rl = r0+i;
            int ii = rl & 15;
            int jl = (rl & 48) + t + (t>=ii ? 1 : 0);
            size_t rg = (size_t)(rbase + rl)*96;
            size_t jg = (size_t)(rbase + jl)*96;
            float2 c0 = Cb2[rg      + lane];
            float2 c1 = Cb2[rg + 32 + lane];
            float2 c2 = Cb2[rg + 64 + lane];
            float2 g0 = G2 [jg      + lane];
            float2 g1 = G2 [jg + 32 + lane];
            float2 g2 = G2 [jg + 64 + lane];
            float ho_lo = hs[rl*68 + lane];
            float ho_hi = hs[rl*68 + 32 + lane];
            float r_lo = sigm(c0.x + g0.x + aR[i].x + br_lo);
            float r_hi = sigm(c0.y + g0.y + aR[i].y + br_hi);
            float z_lo = sigm(c1.x + g1.x + aZ[i].x + bz_lo);
            float z_hi = sigm(c1.y + g1.y + aZ[i].y + bz_hi);
            float n_lo = tanh_(c2.x + g2.x + r_lo*(aN[i].x + bn_lo));
            float n_hi = tanh_(c2.y + g2.y + r_hi*(aN[i].y + bn_hi));
            float hv_lo = (1.0f - z_lo)*n_lo + z_lo*ho_lo;
            float hv_hi = (1.0f - z_hi)*n_hi + z_hi*ho_hi;
            hs[rl*68 + lane]      = hv_lo;
            hs[rl*68 + 32 + lane] = hv_hi;
            l0[i] = hv_lo*w0_lo + hv_hi*w0_hi;
            l1[i] = hv_lo*w1_lo + hv_hi*w1_hi;
        }
        #pragma unroll
        for (int off=16; off>=1; off>>=1){
            #pragma unroll
            for (int i=0;i<8;i++){
                l0[i] += __shfl_xor_sync(0xffffffffu, l0[i], off);
                l1[i] += __shfl_xor_sync(0xffffffffu, l1[i], off);
            }
        }
        #pragma unroll
        for (int i=0;i<8;i++){
            if (lane == i){
                ((u64t*)lout)[(size_t)(rbase + r0 + i)*Tt + t] = pk(l0[i], l1[i]);
            }
        }
    }
}

// =====================================================================
// K3: gumbel hard weights + attention + final GRU cell.
// 512 threads, 64 rows/block, 95KB smem -> 2 blocks/SM.
// Cell GEMM: scalar FFMA, warp owns 4 rows, lane owns cols (lane, lane+32),
// weights via LDG.128 from g_Wc (L1-resident, shared by all blocks).
// =====================================================================
__global__ __launch_bounds__(512,2)
void k_attn_cell(const float* __restrict__ hidden,
                 const float* __restrict__ gum,
                 const float* __restrict__ b_hard,
                 const float* __restrict__ bih_c, const float* __restrict__ bhh_c,
                 float* __restrict__ out)
{
    extern __shared__ float sm[];
    float* qs  = sm;                 // 64*68
    float* ks_ = qs  + 64*68;
    float* vs  = ks_ + 64*68;
    float* hds = vs  + 64*68;
    float* xs  = hds + 64*68;
    float* hw  = xs  + 64*68;        // 64*16
    float* sc  = hw  + 64*16;        // 64*16
    const int tid = threadIdx.x;
    const int rbase = blockIdx.x * 64;

    // vectorized loads: 64 rows x 16 float4 per array
    for (int idx=tid; idx<1024; idx+=512){
        int r=idx>>4, c4=idx&15;
        ((float4*)qs )[r*17+c4] = ((const float4*)g_q)[(rbase+r)*16+c4];
        ((float4*)ks_)[r*17+c4] = ((const float4*)g_k)[(rbase+r)*16+c4];
        ((float4*)vs )[r*17+c4] = ((const float4*)g_v)[(rbase+r)*16+c4];
        ((float4*)hds)[r*17+c4] = ((const float4*)hidden)[(rbase+r)*16+c4];
    }
    {
        const float bh0 = b_hard[0], bh1 = b_hard[1];
        for (int idx=tid; idx<64*Tt; idx+=512){
            int r=idx/Tt, t=idx-r*Tt;
            int row = rbase + r;
            float L0 = g_lf[row*(2*Tt)+2*t]   + g_lb[row*(2*Tt)+2*t]   + bh0;
            float L1 = g_lf[row*(2*Tt)+2*t+1] + g_lb[row*(2*Tt)+2*t+1] + bh1;
            int gi = (row*Tt + t)*2;
            float u0 = gum[gi], u1 = gum[gi+1];
            float gg0 = -logf(-logf(u0+EPSg)+EPSg);
            float gg1 = -logf(-logf(u1+EPSg)+EPSg);
            float dlt = ((L1+gg1)-(L0+gg0)) * 100.0f;   // /TAU
            hw[r*16+t] = 1.0f/(1.0f+__expf(-dlt));
        }
    }
    __syncthreads();

    {   // scores: 8 threads/row, 2 t's each
        int rp = tid>>3, qq = tid&7;
        #pragma unroll
        for (int s2=0; s2<2; ++s2){
            int t = qq + 8*s2;
            if (t < Tt){
                int ii = rp & 15;
                int jl = (rp & 48) + t + (t>=ii ? 1 : 0);
                float dot=0.f;
                #pragma unroll 8
                for (int d=0; d<64; ++d) dot += qs[rp*68+d]*ks_[jl*68+d];
                sc[rp*16+t] = dot*0.125f;
            }
        }
    }
    __syncthreads();
    if (tid < 64){
        int r=tid;
        float m=-1e30f;
        #pragma unroll
        for (int t=0;t<Tt;t++) m = fmaxf(m, sc[r*16+t]);
        float e[Tt]; float ssum=0.f;
        #pragma unroll
        for (int t=0;t<Tt;t++){ e[t]=__expf(sc[r*16+t]-m); ssum+=e[t]; }
        float inv = 1.0f/ssum;
        #pragma unroll
        for (int t=0;t<Tt;t++) sc[r*16+t] = e[t]*inv*hw[r*16+t];
    }
    __syncthreads();
    for (int idx=tid; idx<4096; idx+=512){
        int r=idx>>6, d=idx&63;
        int ii = r & 15, rb2 = r & 48;
        float x=0.f;
        #pragma unroll
        for (int t=0;t<Tt;t++){
            int jl = rb2 + t + (t>=ii ? 1 : 0);
            x += vs[jl*68+d]*sc[r*16+t];
        }
        xs[r*68+d]=x;
    }
    __syncthreads();

    // final GRU cell: warp owns 4 rows, lane owns cols (lane, lane+32)
    const int wid = tid >> 5, lane = tid & 31;
    const int r0 = wid * 4;
    const float4* Wc4 = (const float4*)g_Wc;

    float2 aR[4], aZ[4], aI[4], aH[4];
    #pragma unroll
    for (int i=0;i<4;i++){
        aR[i]=make_float2(0.f,0.f); aZ[i]=make_float2(0.f,0.f);
        aI[i]=make_float2(0.f,0.f); aH[i]=make_float2(0.f,0.f);
    }
    #pragma unroll 2
    for (int dd=0; dd<64; ++dd){
        float4 w0 = Wc4[(dd*3+0)*32 + lane];
        float4 w1 = Wc4[(dd*3+1)*32 + lane];
        float4 w2 = Wc4[(dd*3+2)*32 + lane];
        #pragma unroll
        for (int i=0;i<4;i++){
            float x = xs [(r0+i)*68 + dd];
            float h = hds[(r0+i)*68 + dd];
            aR[i].x += x*w0.x + h*w0.z;  aR[i].y += x*w0.y + h*w0.w;
            aZ[i].x += x*w1.x + h*w1.z;  aZ[i].y += x*w1.y + h*w1.w;
            aI[i].x += x*w2.x;           aI[i].y += x*w2.y;
            aH[i].x += h*w2.z;           aH[i].y += h*w2.w;
        }
    }
    float brc_lo = bih_c[lane]      + bhh_c[lane];
    float brc_hi = bih_c[lane+32]   + bhh_c[lane+32];
    float bzc_lo = bih_c[64+lane]   + bhh_c[64+lane];
    float bzc_hi = bih_c[96+lane]   + bhh_c[96+lane];
    float bni_lo = bih_c[128+lane],  bni_hi = bih_c[160+lane];
    float bnh_lo = bhh_c[128+lane],  bnh_hi = bhh_c[160+lane];
    #pragma unroll
    for (int i=0;i<4;i++){
        int rl = r0+i;
        float ho_lo = hds[rl*68 + lane];
        float ho_hi = hds[rl*68 + 32 + lane];
        float r_lo = sigm(aR[i].x + brc_lo);
        float r_hi = sigm(aR[i].y + brc_hi);
        float z_lo = sigm(aZ[i].x + bzc_lo);
        float z_hi = sigm(aZ[i].y + bzc_hi);
        float n_lo = tanh_(aI[i].x + bni_lo + r_lo*(aH[i].x + bnh_lo));
        float n_hi = tanh_(aI[i].y + bni_hi + r_hi*(aH[i].y + bnh_hi));
        out[(rbase+rl)*64 + lane]      = (1.0f - z_lo)*n_lo + z_lo*ho_lo;
        out[(rbase+rl)*64 + 32 + lane] = (1.0f - z_hi)*n_hi + z_hi*ho_hi;
    }
}

// =====================================================================
extern "C" void kernel_launch(void* const* d_in, const int* in_sizes, int n_in,
                              void* d_out, int out_size)
{
    (void)in_sizes; (void)n_in; (void)out_size;
    const float* obs    = (const float*)d_in[0];
    const float* hidden = (const float*)d_in[1];
    const float* gum    = (const float*)d_in[2];
    const float* W_enc  = (const float*)d_in[3];
    const float* b_enc  = (const float*)d_in[4];
    const float* Wih_f  = (const float*)d_in[5];
    const float* Whh_f  = (const float*)d_in[6];
    const float* bih_f  = (const float*)d_in[7];
    const float* bhh_f  = (const float*)d_in[8];
    const float* Wih_b  = (const float*)d_in[9];
    const float* Whh_b  = (const float*)d_in[10];
    const float* bih_b  = (const float*)d_in[11];
    const float* bhh_b  = (const float*)d_in[12];
    const float* W_hard = (const float*)d_in[13];
    const float* b_hard = (const float*)d_in[14];
    const float* Wq     = (const float*)d_in[15];
    const float* Wk     = (const float*)d_in[16];
    const float* Wv     = (const float*)d_in[17];
    const float* b_v    = (const float*)d_in[18];
    const float* Wih_c  = (const float*)d_in[19];
    const float* Whh_c  = (const float*)d_in[20];
    const float* bih_c  = (const float*)d_in[21];
    const float* bhh_c  = (const float*)d_in[22];
    float* out = (float*)d_out;

    const int sm0 = (64*68 + 4096) * (int)sizeof(float);                    // 33,792 B
    const int sm1 = (64*68 + 4096) * (int)sizeof(float);                    // 33,792 B
    const int sm2 = (12288 + 64*68) * (int)sizeof(float);                   // 66,560 B
    const int sm4 = (5*64*68 + 2*64*16) * (int)sizeof(float);               // 95,232 B

    cudaFuncSetAttribute(k_enc,       cudaFuncAttributeMaxDynamicSharedMemorySize, sm0);
    cudaFuncSetAttribute(k_proj2,     cudaFuncAttributeMaxDynamicSharedMemorySize, sm1);
    cudaFuncSetAttribute(k_gru,       cudaFuncAttributeMaxDynamicSharedMemorySize, sm2);
    cudaFuncSetAttribute(k_attn_cell, cudaFuncAttributeMaxDynamicSharedMemorySize, sm4);

    k_enc<<<256, 256, sm0>>>(obs, W_enc, b_enc);
    k_packW<<<24, 256>>>(Wih_c, Whh_c);
    k_proj2<<<dim3(256,5), 256, sm1>>>(Wq, Wk, Wv, b_v,
                                       Wih_f, bih_f, Wih_b, bih_b);
    k_gru<<<512, 256, sm2>>>(Whh_f, bhh_f, Whh_b, bhh_b, W_hard);
    k_attn_cell<<<256, 512, sm4>>>(hidden, gum, b_hard,
                                   bih_c, bhh_c, out);
}